// round 14
// baseline (speedup 1.0000x reference)
#include <cuda_runtime.h>
#include <cuda_fp16.h>
#include <cstdint>
#include <cstddef>

#define T_STEPS 16
#define B_ROWS  16384
#define HID     512
#define OUT_N   7
#define M_TOT   (T_STEPS * B_ROWS)   /* 262144 */
#define N_CAT   1024
#define K_DIM   512

// ---------------------------------------------------------------------------
// Static device scratch (no runtime allocation)
// ---------------------------------------------------------------------------
__device__ float  g_pre[(size_t)M_TOT * N_CAT];     // [T*B, 1024] pre-activations
__device__ __half g_ws0[(size_t)N_CAT * K_DIM];     // (1024*W)^T hi split, [N,K]
__device__ __half g_ws1[(size_t)N_CAT * K_DIM];     // (1024*W)^T lo split
__device__ float  g_bias[N_CAT];

// ---------------------------------------------------------------------------
// Helpers — baseline PTX (sm_80+, valid in every compilation pass)
// ---------------------------------------------------------------------------
__device__ __forceinline__ uint32_t smem_u32(const void* p) {
    uint32_t a;
    asm("{ .reg .u64 t; cvta.to.shared.u64 t, %1; cvt.u32.u64 %0, t; }" : "=r"(a) : "l"(p));
    return a;
}
__device__ __forceinline__ void cp16(uint32_t dst, const void* src) {
    asm volatile("cp.async.cg.shared.global [%0], [%1], 16;" :: "r"(dst), "l"(src) : "memory");
}
__device__ __forceinline__ void cp_commit() {
    asm volatile("cp.async.commit_group;" ::: "memory");
}
__device__ __forceinline__ void cp_wait0() {
    asm volatile("cp.async.wait_group 0;" ::: "memory");
}
__device__ __forceinline__ void cp_wait1() {
    asm volatile("cp.async.wait_group 1;" ::: "memory");
}
__device__ __forceinline__ void ldsm4(uint32_t* r, uint32_t addr) {
    asm volatile("ldmatrix.sync.aligned.m8n8.x4.shared.b16 {%0,%1,%2,%3}, [%4];"
                 : "=r"(r[0]), "=r"(r[1]), "=r"(r[2]), "=r"(r[3]) : "r"(addr));
}
__device__ __forceinline__ void mma16816(float* c, const uint32_t* a, const uint32_t* b) {
    asm volatile("mma.sync.aligned.m16n8k16.row.col.f32.f16.f16.f32 "
                 "{%0,%1,%2,%3}, {%4,%5,%6,%7}, {%8,%9}, {%0,%1,%2,%3};"
                 : "+f"(c[0]), "+f"(c[1]), "+f"(c[2]), "+f"(c[3])
                 : "r"(a[0]), "r"(a[1]), "r"(a[2]), "r"(a[3]), "r"(b[0]), "r"(b[1]));
}
__device__ __forceinline__ uint32_t sw64(uint32_t off) {
    return off ^ ((off >> 3) & 0x30);
}
// split one float4 into hi/lo fp16 pairs (uint2 each)
__device__ __forceinline__ void split4(float4 v, uint2& hi, uint2& lo) {
    union { __half h[4]; uint2 u; } p0, p1;
    float f[4] = {v.x, v.y, v.z, v.w};
    #pragma unroll
    for (int k = 0; k < 4; k++) {
        __half a = __float2half_rn(f[k]);
        float  r = f[k] - __half2float(a);
        p0.h[k] = a;
        p1.h[k] = __float2half_rn(r);
    }
    hi = p0.u; lo = p1.u;
}

// ---------------------------------------------------------------------------
// Helpers — sm_103a-only (feature-guarded; absent from compute_103 PTX)
// ---------------------------------------------------------------------------
#if defined(__CUDA_ARCH_FEAT_SM103_ALL)
__device__ __forceinline__ bool elect1() {
    uint32_t p;
    asm volatile("{ .reg .pred P; elect.sync _|P, 0xFFFFFFFF; selp.b32 %0, 1, 0, P; }" : "=r"(p));
    return p != 0;
}
__device__ __forceinline__ void mbar_init(uint32_t mbar, uint32_t cnt) {
    asm volatile("mbarrier.init.shared.b64 [%0], %1;" :: "r"(mbar), "r"(cnt) : "memory");
}
__device__ __forceinline__ void mbar_wait(uint32_t mbar, uint32_t parity) {
    asm volatile(
        "{\n\t.reg .pred P;\n\t"
        "LW_%=:\n\t"
        "mbarrier.try_wait.parity.acquire.cta.shared::cta.b64 P, [%0], %1, 0x989680;\n\t"
        "@P bra.uni LD_%=;\n\t"
        "bra.uni LW_%=;\n\t"
        "LD_%=:\n\t}"
        :: "r"(mbar), "r"(parity) : "memory");
}
__device__ __forceinline__ void tmem_alloc(uint32_t dst_smem, uint32_t ncols) {
    asm volatile("tcgen05.alloc.cta_group::1.sync.aligned.shared::cta.b32 [%0], %1;"
                 :: "r"(dst_smem), "r"(ncols) : "memory");
}
__device__ __forceinline__ void tmem_relinquish() {
    asm volatile("tcgen05.relinquish_alloc_permit.cta_group::1.sync.aligned;" ::: "memory");
}
__device__ __forceinline__ void tmem_dealloc(uint32_t tmem, uint32_t ncols) {
    asm volatile("tcgen05.dealloc.cta_group::1.sync.aligned.b32 %0, %1;" :: "r"(tmem), "r"(ncols));
}
__device__ __forceinline__ void mma_f16_ss(uint32_t d, uint64_t ad, uint64_t bd,
                                           uint32_t idesc, uint32_t en) {
    asm volatile(
        "{\n\t.reg .pred p;\n\t"
        "setp.ne.u32 p, %4, 0;\n\t"
        "tcgen05.mma.cta_group::1.kind::f16 [%0], %1, %2, %3, {%5, %5, %5, %5}, p;\n\t}"
        :: "r"(d), "l"(ad), "l"(bd), "r"(idesc), "r"(en), "r"(0u) : "memory");
}
__device__ __forceinline__ void mma_commit(uint32_t mbar) {
    asm volatile("tcgen05.commit.cta_group::1.mbarrier::arrive::one.shared::cluster.b64 [%0];"
                 :: "r"(mbar) : "memory");
}
__device__ __forceinline__ void fence_async_shared() {
    asm volatile("fence.proxy.async.shared::cta;" ::: "memory");
}
__device__ __forceinline__ void tcgen05_fence_after() {
    asm volatile("tcgen05.fence::after_thread_sync;" ::: "memory");
}
__device__ __forceinline__ void tmem_wait_ld() {
    asm volatile("tcgen05.wait::ld.sync.aligned;" ::: "memory");
}
#define LDTM_X32(r, addr) \
    asm volatile( \
        "tcgen05.ld.sync.aligned.32x32b.x32.b32 " \
        "{%0, %1, %2, %3, %4, %5, %6, %7, " \
        " %8, %9, %10, %11, %12, %13, %14, %15, " \
        " %16, %17, %18, %19, %20, %21, %22, %23, " \
        " %24, %25, %26, %27, %28, %29, %30, %31}, [%32];" \
        : "=r"((r)[0]),  "=r"((r)[1]),  "=r"((r)[2]),  "=r"((r)[3]), \
          "=r"((r)[4]),  "=r"((r)[5]),  "=r"((r)[6]),  "=r"((r)[7]), \
          "=r"((r)[8]),  "=r"((r)[9]),  "=r"((r)[10]), "=r"((r)[11]), \
          "=r"((r)[12]), "=r"((r)[13]), "=r"((r)[14]), "=r"((r)[15]), \
          "=r"((r)[16]), "=r"((r)[17]), "=r"((r)[18]), "=r"((r)[19]), \
          "=r"((r)[20]), "=r"((r)[21]), "=r"((r)[22]), "=r"((r)[23]), \
          "=r"((r)[24]), "=r"((r)[25]), "=r"((r)[26]), "=r"((r)[27]), \
          "=r"((r)[28]), "=r"((r)[29]), "=r"((r)[30]), "=r"((r)[31]) \
        : "r"(addr))

// SW64 K-major descriptor: layout=4, version=1 (Blackwell), SBO=32, LBO=1.
static constexpr uint64_t DESC_BASE_SW64 =
    (4ULL << 61) | (1ULL << 46) | (32ULL << 32) | (1ULL << 16);
__device__ __forceinline__ uint64_t mkdesc64(uint32_t base) {
    return DESC_BASE_SW64 | (uint64_t)((base >> 4) & 0x3FFF);
}
#endif  // __CUDA_ARCH_FEAT_SM103_ALL

// ---------------------------------------------------------------------------
// Weight split conversion (2 MB — stays a tiny standalone kernel)
// ---------------------------------------------------------------------------
__global__ void convert_w_kernel(const float* __restrict__ W_gc, const float* __restrict__ W_d1,
                                 const float* __restrict__ b_gc, const float* __restrict__ b_d1)
{
    int i = blockIdx.x * blockDim.x + threadIdx.x;   // 524288
    int n = i >> 9, k = i & 511;
    float w = (n < HID) ? W_gc[k * HID + n] : W_d1[k * HID + (n - HID)];
    w *= 1024.0f;            // exact pow2 scale; keeps lo-split out of fp16 subnormals
    __half a = __float2half_rn(w);
    float  r = w - __half2float(a);
    g_ws0[(size_t)n * K_DIM + k] = a;
    g_ws1[(size_t)n * K_DIM + k] = __float2half_rn(r);
    if (i < N_CAT) g_bias[i] = (i < HID) ? b_gc[i] : b_d1[i - HID];
}

// ---------------------------------------------------------------------------
// GEMM: g_pre = (x @ (w0+w1)^T) * 2^-10 + bias with in-kernel fp16 split of x.
// CTA tile 256x128 (two 128x128 TMEM accumulators = 256 cols). KC=32, SW64,
// 2-stage ring, 2 CTAs/SM: the peer CTA's MMA stream fills every bubble
// (prologue, epilogue, restage drain). R8-proven sync: syncthreads + done-mbar.
// ---------------------------------------------------------------------------
#define GM 256
#define GN 128
#define KC 32
#define NCHUNK (K_DIM / KC)               /* 16 */
#define STAGE_BYTES 49152                 /* A0 16K | A1 16K | B0 8K | B1 8K */
#define GEMM_SMEM (1024 + 2 * STAGE_BYTES)   /* 99328 */

__global__ void __launch_bounds__(256, 2) gemm_kernel(const float* __restrict__ x)
{
    extern __shared__ char smem[];
    const int tid  = threadIdx.x;
    const int lane = tid & 31;
    const int wid  = tid >> 5;
    const size_t m0 = (size_t)blockIdx.y * GM;
    const int    n0 = blockIdx.x * GN;

#if defined(__CUDA_ARCH_FEAT_SM103_ALL)
    // ======================= tcgen05 path (sm_103a) =======================
    __shared__ __align__(16) uint32_t s_ctrl[8];  // [0]=tmem ptr; [2..5]=2 done mbars
    char* tp = (char*)(((uintptr_t)smem + 1023) & ~(uintptr_t)1023);
    const uint32_t SAu   = smem_u32(tp);
    const uint32_t ctrl  = smem_u32(&s_ctrl[0]);
    const uint32_t mbar0 = smem_u32(&s_ctrl[2]);   // done[s] = mbar0 + 8*s

    if (wid == 0) {
        tmem_alloc(ctrl, 256);
        tmem_relinquish();                          // let the co-resident CTA allocate
    }
    if (tid == 0) {
        mbar_init(mbar0, 1);
        mbar_init(mbar0 + 8, 1);
    }
    __syncthreads();
    uint32_t tmem;
    asm volatile("ld.shared.b32 %0, [%1];" : "=r"(tmem) : "r"(ctrl));

    const uint32_t IDESC = (1u << 4) | ((GN / 8) << 17) | (8u << 24);   // M=128,N=128,f16

    auto load_b = [&](int c) {                       // B: 1024 x 16B via cp.async
        char* base = tp + (c & 1) * STAGE_BYTES;
        #pragma unroll
        for (int i = 0; i < 4; i++) {
            int u = tid + 256 * i;
            int p = u >> 9, rem = u & 511, row = rem >> 2, j = rem & 3;
            const __half* sbp = (p ? g_ws1 : g_ws0) + (size_t)(n0 + row) * K_DIM + c * KC + j * 8;
            cp16(smem_u32(base + 32768 + p * 8192 + sw64(row * 64 + j * 16)), sbp);
        }
        cp_commit();
    };

    auto ldg_a = [&](int c, float4* xr) {            // A fp32 -> registers (8 LDG.128)
        #pragma unroll
        for (int i = 0; i < 8; i++) {
            int u = tid + 256 * i;
            int row = u >> 3, jj = u & 7;
            xr[i] = *(const float4*)(x + (m0 + row) * K_DIM + c * KC + 4 * jj);
        }
    };
    auto sts_a = [&](int c, const float4* xr) {      // split + store to SW64 planes
        char* base = tp + (c & 1) * STAGE_BYTES;
        #pragma unroll
        for (int i = 0; i < 8; i++) {
            int u = tid + 256 * i;
            int row = u >> 3, jj = u & 7;
            uint2 hi, lo;
            split4(xr[i], hi, lo);
            uint32_t off = sw64(row * 64 + jj * 8);
            *(uint2*)(base + off)         = hi;      // plane A0
            *(uint2*)(base + 16384 + off) = lo;      // plane A1
        }
    };

    // prologue: chunks 0,1 staged (stages fresh, no waits)
    {
        float4 t0[8], t1[8];
        ldg_a(0, t0);
        ldg_a(1, t1);
        load_b(0);
        load_b(1);
        sts_a(0, t0);
        sts_a(1, t1);
    }

    #pragma unroll 1
    for (int c = 0; c < NCHUNK; c++) {
        float4 xr[8];
        if (c + 2 < NCHUNK) ldg_a(c + 2, xr);        // issue LDGs at top

        if (c < NCHUNK - 1) cp_wait1(); else cp_wait0();   // B(c) landed
        fence_async_shared();
        __syncthreads();                              // A STS for chunk c visible

        if (wid == 0 && elect1()) {
            uint32_t sb = SAu + (c & 1) * STAGE_BYTES;
            #pragma unroll
            for (int ks = 0; ks < 2; ks++) {
                #pragma unroll
                for (int h = 0; h < 2; h++) {
                    uint64_t dA0 = mkdesc64(sb + h * 8192) + 2 * ks;
                    uint64_t dA1 = mkdesc64(sb + 16384 + h * 8192) + 2 * ks;
                    uint64_t dB0 = mkdesc64(sb + 32768) + 2 * ks;
                    uint64_t dB1 = mkdesc64(sb + 40960) + 2 * ks;
                    uint32_t d   = tmem + 128 * h;
                    uint32_t en  = (c == 0 && ks == 0) ? 0u : 1u;
                    mma_f16_ss(d, dA0, dB0, IDESC, en);
                    mma_f16_ss(d, dA0, dB1, IDESC, 1u);
                    mma_f16_ss(d, dA1, dB0, IDESC, 1u);
                }
            }
            mma_commit(mbar0 + 8 * (c & 1));
        }

        if (c + 2 < NCHUNK) {
            // stage (c+2)&1 == c&1 is being read by chunk c's MMAs: drain them
            mbar_wait(mbar0 + 8 * (c & 1), (c / 2) & 1);
            sts_a(c + 2, xr);                         // consume top LDGs
            load_b(c + 2);                            // async B
        }
    }
    // drain tail chunks 14 (s=0, phase 7 -> parity 1) and 15 (s=1, phase 7 -> 1)
    mbar_wait(mbar0 + 0, 1);
    mbar_wait(mbar0 + 8, 1);
    tcgen05_fence_after();

    // epilogue: warp w -> half h=w>>2 (rows m0+128h+32*(w&3)), cols n0..n0+127
    {
        int h = wid >> 2, sub = wid & 3;
        size_t row = m0 + h * 128 + sub * 32 + lane;
        float* cp = g_pre + row * N_CAT + n0;
        const float sc = 1.0f / 1024.0f;
        #pragma unroll
        for (int cb = 0; cb < 4; cb += 2) {
            uint32_t r0[32], r1[32];
            LDTM_X32(r0, tmem + 128 * h + cb * 32);
            LDTM_X32(r1, tmem + 128 * h + cb * 32 + 32);
            tmem_wait_ld();
            #pragma unroll
            for (int j = 0; j < 32; j += 4) {
                float4 v;
                v.x = __uint_as_float(r0[j + 0]) * sc + g_bias[n0 + cb * 32 + j + 0];
                v.y = __uint_as_float(r0[j + 1]) * sc + g_bias[n0 + cb * 32 + j + 1];
                v.z = __uint_as_float(r0[j + 2]) * sc + g_bias[n0 + cb * 32 + j + 2];
                v.w = __uint_as_float(r0[j + 3]) * sc + g_bias[n0 + cb * 32 + j + 3];
                *(float4*)(cp + cb * 32 + j) = v;
            }
            #pragma unroll
            for (int j = 0; j < 32; j += 4) {
                float4 v;
                v.x = __uint_as_float(r1[j + 0]) * sc + g_bias[n0 + (cb + 1) * 32 + j + 0];
                v.y = __uint_as_float(r1[j + 1]) * sc + g_bias[n0 + (cb + 1) * 32 + j + 1];
                v.z = __uint_as_float(r1[j + 2]) * sc + g_bias[n0 + (cb + 1) * 32 + j + 2];
                v.w = __uint_as_float(r1[j + 3]) * sc + g_bias[n0 + (cb + 1) * 32 + j + 3];
                *(float4*)(cp + (cb + 1) * 32 + j) = v;
            }
        }
    }
    __syncthreads();
    if (wid == 0) tmem_dealloc(tmem, 256);

#else
    // ========= HMMA fallback (compute_103): two 128x128 sub-tiles =========
    const uint32_t sb = smem_u32(smem);
    const int wm = (wid >> 2) * 64;
    const int wn = (wid & 3) * 32;
    #define ROWB 80
    #define SPL_BYTES (128 * ROWB)
    #define HSTAGE (4 * SPL_BYTES)

    #pragma unroll 1
    for (int mh = 0; mh < 2; mh++) {
        const size_t m0h = m0 + 128 * mh;
        const int n0h = n0;

        float c[4][4][4];
        #pragma unroll
        for (int i = 0; i < 4; i++)
            #pragma unroll
            for (int j = 0; j < 4; j++)
                #pragma unroll
                for (int k = 0; k < 4; k++) c[i][j][k] = 0.f;

        auto load_stage = [&](int cc, int st) {
            char* basep = smem + st * HSTAGE;
            uint32_t base = sb + st * HSTAGE;
            #pragma unroll
            for (int i = 0; i < 4; i++) {
                int u = tid + 256 * i;
                int r = u >> 3, jj = u & 7;
                float4 xv = *(const float4*)(x + (m0h + r) * K_DIM + cc * 32 + 4 * jj);
                uint2 hi, lo;
                split4(xv, hi, lo);
                *(uint2*)(basep + r * ROWB + jj * 8)             = hi;
                *(uint2*)(basep + SPL_BYTES + r * ROWB + jj * 8) = lo;
            }
            #pragma unroll
            for (int i = 0; i < 4; i++) {
                int u = tid + 256 * i;
                int p = u >> 9, r = (u >> 2) & 127, j = u & 3;
                const __half* src = (p ? g_ws1 : g_ws0) + (size_t)(n0h + r) * K_DIM + cc * 32 + j * 8;
                cp16(base + 2 * SPL_BYTES + p * SPL_BYTES + r * ROWB + j * 16, src);
            }
            cp_commit();
        };

        auto compute_stage = [&](int st) {
            uint32_t Ab = sb + st * HSTAGE;
            uint32_t Bb = Ab + 2 * SPL_BYTES;
            #pragma unroll
            for (int kk = 0; kk < 2; kk++) {
                uint32_t a[2][4][4];
                uint32_t b[2][4][2];
                #pragma unroll
                for (int p = 0; p < 2; p++)
                    #pragma unroll
                    for (int mi = 0; mi < 4; mi++) {
                        uint32_t addr = Ab + p * SPL_BYTES
                                      + (wm + 16 * mi + (lane & 15)) * ROWB
                                      + kk * 32 + (lane >> 4) * 16;
                        ldsm4(a[p][mi], addr);
                    }
                #pragma unroll
                for (int p = 0; p < 2; p++)
                    #pragma unroll
                    for (int jj = 0; jj < 2; jj++) {
                        uint32_t nr = wn + 16 * jj + ((lane >> 4) & 1) * 8 + (lane & 7);
                        uint32_t addr = Bb + p * SPL_BYTES + nr * ROWB
                                      + kk * 32 + ((lane >> 3) & 1) * 16;
                        uint32_t r4[4];
                        ldsm4(r4, addr);
                        b[p][2 * jj][0]     = r4[0]; b[p][2 * jj][1]     = r4[1];
                        b[p][2 * jj + 1][0] = r4[2]; b[p][2 * jj + 1][1] = r4[3];
                    }
                #pragma unroll
                for (int mi = 0; mi < 4; mi++)
                    #pragma unroll
                    for (int nj = 0; nj < 4; nj++) {
                        mma16816(c[mi][nj], a[0][mi], b[0][nj]);
                        mma16816(c[mi][nj], a[0][mi], b[1][nj]);
                        mma16816(c[mi][nj], a[1][mi], b[0][nj]);
                    }
            }
        };

        load_stage(0, 0);
        #pragma unroll 1
        for (int cc = 0; cc < K_DIM / 32; cc++) {
            cp_wait0();
            __syncthreads();
            if (cc + 1 < K_DIM / 32) load_stage(cc + 1, (cc + 1) & 1);
            compute_stage(cc & 1);
        }
        __syncthreads();

        const float sc = 1.0f / 1024.0f;
        const int g = lane >> 2, t4 = lane & 3;
        #pragma unroll
        for (int mi = 0; mi < 4; mi++) {
            #pragma unroll
            for (int nj = 0; nj < 4; nj++) {
                int col = n0h + wn + 8 * nj + t4 * 2;
                float b0 = g_bias[col], b1 = g_bias[col + 1];
                size_t row = m0h + wm + 16 * mi + g;
                float2 v0 = {c[mi][nj][0] * sc + b0, c[mi][nj][1] * sc + b1};
                *(float2*)(g_pre + row * N_CAT + col) = v0;
                float2 v1 = {c[mi][nj][2] * sc + b0, c[mi][nj][3] * sc + b1};
                *(float2*)(g_pre + (row + 8) * N_CAT + col) = v1;
            }
        }
    }
    #undef ROWB
    #undef SPL_BYTES
    #undef HSTAGE
#endif
}

// ---------------------------------------------------------------------------
// Recurrence: one WARP per batch row, warp-synchronous (no smem, no barriers).
// Lane l owns neurons j = 128m + 4l + q (m,q in 0..3).
// ---------------------------------------------------------------------------
__global__ void __launch_bounds__(128) recur_kernel(
    const float* __restrict__ W_pc, const float* __restrict__ b_pc,
    const float* __restrict__ W_d1, const float* __restrict__ W_d2,
    const float* __restrict__ b_d2, float* __restrict__ out)
{
    const int wid  = threadIdx.x >> 5;
    const int l    = threadIdx.x & 31;
    const int r    = blockIdx.x * 4 + wid;      // batch row

    float m1[16], m2[16], m3[16];
    #pragma unroll
    for (int i = 0; i < 16; i++) { m1[i] = 0.f; m2[i] = 0.f; m3[i] = 0.f; }
    float oacc[OUT_N] = {0.f, 0.f, 0.f, 0.f, 0.f, 0.f, 0.f};

    for (int t = 0; t < T_STEPS; t++) {
        const float* pre = g_pre + ((size_t)t * B_ROWS + r) * N_CAT;
        unsigned bal[16];

        // ---- LIF1 (input = precomputed x@W_gc + b_gc) ----
        #pragma unroll
        for (int m = 0; m < 4; m++) {
            float4 p = *(const float4*)(pre + 128 * m + 4 * l);
            float pv[4] = {p.x, p.y, p.z, p.w};
            #pragma unroll
            for (int q = 0; q < 4; q++) {
                float v = 0.5f * (m1[4 * m + q] + pv[q]);
                bool  s = v > 1.0f;
                m1[4 * m + q] = s ? 0.f : v;
                bal[4 * m + q] = __ballot_sync(0xffffffffu, s);
            }
        }

        // ---- pc_pre = gc @ W_pc + b_pc (sparse row gather) ----
        float a2[16];
        #pragma unroll
        for (int m = 0; m < 4; m++) {
            float4 bv = *(const float4*)(b_pc + 128 * m + 4 * l);
            a2[4 * m + 0] = bv.x; a2[4 * m + 1] = bv.y;
            a2[4 * m + 2] = bv.z; a2[4 * m + 3] = bv.w;
        }
        #pragma unroll
        for (int mw = 0; mw < 16; mw++) {
            unsigned mm = bal[mw];
            while (mm) {
                int bit = __ffs(mm) - 1;
                mm &= mm - 1;
                int row2 = 128 * (mw >> 2) + 4 * bit + (mw & 3);
                const float* wr = W_pc + (size_t)row2 * HID;
                #pragma unroll
                for (int m = 0; m < 4; m++) {
                    float4 wv = *(const float4*)(wr + 128 * m + 4 * l);
                    a2[4 * m + 0] += wv.x; a2[4 * m + 1] += wv.y;
                    a2[4 * m + 2] += wv.z; a2[4 * m + 3] += wv.w;
                }
            }
        }

        // ---- LIF2 ----
        #pragma unroll
        for (int i = 0; i < 16; i++) {
            float v = 0.5f * (m2[i] + a2[i]);
            bool  s = v > 1.0f;
            m2[i] = s ? 0.f : v;
            bal[i] = __ballot_sync(0xffffffffu, s);
        }

        // ---- d1_pre = precomputed x-part + pc @ W_d1_bottom ----
        float a3[16];
        #pragma unroll
        for (int m = 0; m < 4; m++) {
            float4 p = *(const float4*)(pre + HID + 128 * m + 4 * l);
            a3[4 * m + 0] = p.x; a3[4 * m + 1] = p.y;
            a3[4 * m + 2] = p.z; a3[4 * m + 3] = p.w;
        }
        #pragma unroll
        for (int mw = 0; mw < 16; mw++) {
            unsigned mm = bal[mw];
            while (mm) {
                int bit = __ffs(mm) - 1;
                mm &= mm - 1;
                int row2 = HID + 128 * (mw >> 2) + 4 * bit + (mw & 3);
                const float* wr = W_d1 + (size_t)row2 * HID;
                #pragma unroll
                for (int m = 0; m < 4; m++) {
                    float4 wv = *(const float4*)(wr + 128 * m + 4 * l);
                    a3[4 * m + 0] += wv.x; a3[4 * m + 1] += wv.y;
                    a3[4 * m + 2] += wv.z; a3[4 * m + 3] += wv.w;
                }
            }
        }

        // ---- LIF3 -> readout ----
        #pragma unroll
        for (int i = 0; i < 16; i++) {
            float v = 0.5f * (m3[i] + a3[i]);
            bool  s = v > 1.0f;
            m3[i] = s ? 0.f : v;
            if (s) {
                int j = 128 * (i >> 2) + 4 * l + (i & 3);
                const float* wr = W_d2 + (size_t)j * OUT_N;
                #pragma unroll
                for (int o = 0; o < OUT_N; o++) oacc[o] += wr[o];
            }
        }
    }

    // ---- warp reduction of 7 outputs ----
    #pragma unroll
    for (int o = 0; o < OUT_N; o++) {
        float v = oacc[o];
        #pragma unroll
        for (int off = 16; off; off >>= 1) v += __shfl_down_sync(0xffffffffu, v, off);
        if (l == 0) out[(size_t)r * OUT_N + o] = v * (1.0f / (float)T_STEPS) + b_d2[o];
    }
}

// ---------------------------------------------------------------------------
extern "C" void kernel_launch(void* const* d_in, const int* in_sizes, int n_in,
                              void* d_out, int out_size)
{
    const float* x    = (const float*)d_in[0];
    const float* W_gc = (const float*)d_in[1];
    const float* b_gc = (const float*)d_in[2];
    const float* W_pc = (const float*)d_in[3];
    const float* b_pc = (const float*)d_in[4];
    const float* W_d1 = (const float*)d_in[5];
    const float* b_d1 = (const float*)d_in[6];
    const float* W_d2 = (const float*)d_in[7];
    const float* b_d2 = (const float*)d_in[8];
    float* out = (float*)d_out;
    (void)in_sizes; (void)n_in; (void)out_size;

    cudaFuncSetAttribute(gemm_kernel, cudaFuncAttributeMaxDynamicSharedMemorySize, GEMM_SMEM);

    convert_w_kernel<<<(N_CAT * K_DIM) / 256, 256>>>(W_gc, W_d1, b_gc, b_d1);

    dim3 grid(N_CAT / GN, M_TOT / GM);   // (8, 1024); x fastest -> co-resident CTAs share A
    gemm_kernel<<<grid, 256, GEMM_SMEM>>>(x);

    recur_kernel<<<B_ROWS / 4, 128>>>(W_pc, b_pc, W_d1, W_d2, b_d2, out);
}

// round 15
// speedup vs baseline: 1.1848x; 1.1848x over previous
#include <cuda_runtime.h>
#include <cuda_fp16.h>
#include <cstdint>
#include <cstddef>

#define T_STEPS 16
#define B_ROWS  16384
#define HID     512
#define OUT_N   7
#define M_TOT   (T_STEPS * B_ROWS)   /* 262144 */
#define N_CAT   1024
#define K_DIM   512

// ---------------------------------------------------------------------------
// Static device scratch (no runtime allocation)
// ---------------------------------------------------------------------------
__device__ float  g_pre[(size_t)M_TOT * N_CAT];     // [T*B, 1024] pre-activations
__device__ __half g_ws0[(size_t)N_CAT * K_DIM];     // (1024*W)^T hi split, [N,K]
__device__ __half g_ws1[(size_t)N_CAT * K_DIM];     // (1024*W)^T lo split
__device__ float  g_bias[N_CAT];

// ---------------------------------------------------------------------------
// Helpers — baseline PTX (sm_80+, valid in every compilation pass)
// ---------------------------------------------------------------------------
__device__ __forceinline__ uint32_t smem_u32(const void* p) {
    uint32_t a;
    asm("{ .reg .u64 t; cvta.to.shared.u64 t, %1; cvt.u32.u64 %0, t; }" : "=r"(a) : "l"(p));
    return a;
}
__device__ __forceinline__ void cp16(uint32_t dst, const void* src) {
    asm volatile("cp.async.cg.shared.global [%0], [%1], 16;" :: "r"(dst), "l"(src) : "memory");
}
__device__ __forceinline__ void cp_commit() {
    asm volatile("cp.async.commit_group;" ::: "memory");
}
__device__ __forceinline__ void cp_wait0() {
    asm volatile("cp.async.wait_group 0;" ::: "memory");
}
__device__ __forceinline__ void cp_wait1() {
    asm volatile("cp.async.wait_group 1;" ::: "memory");
}
__device__ __forceinline__ void ldsm4(uint32_t* r, uint32_t addr) {
    asm volatile("ldmatrix.sync.aligned.m8n8.x4.shared.b16 {%0,%1,%2,%3}, [%4];"
                 : "=r"(r[0]), "=r"(r[1]), "=r"(r[2]), "=r"(r[3]) : "r"(addr));
}
__device__ __forceinline__ void mma16816(float* c, const uint32_t* a, const uint32_t* b) {
    asm volatile("mma.sync.aligned.m16n8k16.row.col.f32.f16.f16.f32 "
                 "{%0,%1,%2,%3}, {%4,%5,%6,%7}, {%8,%9}, {%0,%1,%2,%3};"
                 : "+f"(c[0]), "+f"(c[1]), "+f"(c[2]), "+f"(c[3])
                 : "r"(a[0]), "r"(a[1]), "r"(a[2]), "r"(a[3]), "r"(b[0]), "r"(b[1]));
}
__device__ __forceinline__ uint32_t sw64(uint32_t off) {
    return off ^ ((off >> 3) & 0x30);
}
// split one float4 into hi/lo fp16 pairs (uint2 each)
__device__ __forceinline__ void split4(float4 v, uint2& hi, uint2& lo) {
    union { __half h[4]; uint2 u; } p0, p1;
    float f[4] = {v.x, v.y, v.z, v.w};
    #pragma unroll
    for (int k = 0; k < 4; k++) {
        __half a = __float2half_rn(f[k]);
        float  r = f[k] - __half2float(a);
        p0.h[k] = a;
        p1.h[k] = __float2half_rn(r);
    }
    hi = p0.u; lo = p1.u;
}

// ---------------------------------------------------------------------------
// Helpers — sm_103a-only (feature-guarded; absent from compute_103 PTX)
// ---------------------------------------------------------------------------
#if defined(__CUDA_ARCH_FEAT_SM103_ALL)
__device__ __forceinline__ bool elect1() {
    uint32_t p;
    asm volatile("{ .reg .pred P; elect.sync _|P, 0xFFFFFFFF; selp.b32 %0, 1, 0, P; }" : "=r"(p));
    return p != 0;
}
__device__ __forceinline__ void mbar_init(uint32_t mbar, uint32_t cnt) {
    asm volatile("mbarrier.init.shared.b64 [%0], %1;" :: "r"(mbar), "r"(cnt) : "memory");
}
__device__ __forceinline__ void mbar_wait(uint32_t mbar, uint32_t parity) {
    asm volatile(
        "{\n\t.reg .pred P;\n\t"
        "LW_%=:\n\t"
        "mbarrier.try_wait.parity.acquire.cta.shared::cta.b64 P, [%0], %1, 0x989680;\n\t"
        "@P bra.uni LD_%=;\n\t"
        "bra.uni LW_%=;\n\t"
        "LD_%=:\n\t}"
        :: "r"(mbar), "r"(parity) : "memory");
}
__device__ __forceinline__ void tmem_alloc(uint32_t dst_smem, uint32_t ncols) {
    asm volatile("tcgen05.alloc.cta_group::1.sync.aligned.shared::cta.b32 [%0], %1;"
                 :: "r"(dst_smem), "r"(ncols) : "memory");
}
__device__ __forceinline__ void tmem_dealloc(uint32_t tmem, uint32_t ncols) {
    asm volatile("tcgen05.relinquish_alloc_permit.cta_group::1.sync.aligned;" ::: "memory");
    asm volatile("tcgen05.dealloc.cta_group::1.sync.aligned.b32 %0, %1;" :: "r"(tmem), "r"(ncols));
}
__device__ __forceinline__ void mma_f16_ss(uint32_t d, uint64_t ad, uint64_t bd,
                                           uint32_t idesc, uint32_t en) {
    asm volatile(
        "{\n\t.reg .pred p;\n\t"
        "setp.ne.u32 p, %4, 0;\n\t"
        "tcgen05.mma.cta_group::1.kind::f16 [%0], %1, %2, %3, {%5, %5, %5, %5}, p;\n\t}"
        :: "r"(d), "l"(ad), "l"(bd), "r"(idesc), "r"(en), "r"(0u) : "memory");
}
__device__ __forceinline__ void mma_commit(uint32_t mbar) {
    asm volatile("tcgen05.commit.cta_group::1.mbarrier::arrive::one.shared::cluster.b64 [%0];"
                 :: "r"(mbar) : "memory");
}
__device__ __forceinline__ void fence_async_shared() {
    asm volatile("fence.proxy.async.shared::cta;" ::: "memory");
}
__device__ __forceinline__ void tcgen05_fence_after() {
    asm volatile("tcgen05.fence::after_thread_sync;" ::: "memory");
}
__device__ __forceinline__ void tmem_wait_ld() {
    asm volatile("tcgen05.wait::ld.sync.aligned;" ::: "memory");
}
#define LDTM_X32(r, addr) \
    asm volatile( \
        "tcgen05.ld.sync.aligned.32x32b.x32.b32 " \
        "{%0, %1, %2, %3, %4, %5, %6, %7, " \
        " %8, %9, %10, %11, %12, %13, %14, %15, " \
        " %16, %17, %18, %19, %20, %21, %22, %23, " \
        " %24, %25, %26, %27, %28, %29, %30, %31}, [%32];" \
        : "=r"((r)[0]),  "=r"((r)[1]),  "=r"((r)[2]),  "=r"((r)[3]), \
          "=r"((r)[4]),  "=r"((r)[5]),  "=r"((r)[6]),  "=r"((r)[7]), \
          "=r"((r)[8]),  "=r"((r)[9]),  "=r"((r)[10]), "=r"((r)[11]), \
          "=r"((r)[12]), "=r"((r)[13]), "=r"((r)[14]), "=r"((r)[15]), \
          "=r"((r)[16]), "=r"((r)[17]), "=r"((r)[18]), "=r"((r)[19]), \
          "=r"((r)[20]), "=r"((r)[21]), "=r"((r)[22]), "=r"((r)[23]), \
          "=r"((r)[24]), "=r"((r)[25]), "=r"((r)[26]), "=r"((r)[27]), \
          "=r"((r)[28]), "=r"((r)[29]), "=r"((r)[30]), "=r"((r)[31]) \
        : "r"(addr))

// SW64 K-major descriptor: layout=4, version=1 (Blackwell), SBO=32, LBO=1.
static constexpr uint64_t DESC_BASE_SW64 =
    (4ULL << 61) | (1ULL << 46) | (32ULL << 32) | (1ULL << 16);
__device__ __forceinline__ uint64_t mkdesc64(uint32_t base) {
    return DESC_BASE_SW64 | (uint64_t)((base >> 4) & 0x3FFF);
}
#endif  // __CUDA_ARCH_FEAT_SM103_ALL

// ---------------------------------------------------------------------------
// Weight split conversion (2 MB — stays a tiny standalone kernel)
// ---------------------------------------------------------------------------
__global__ void convert_w_kernel(const float* __restrict__ W_gc, const float* __restrict__ W_d1,
                                 const float* __restrict__ b_gc, const float* __restrict__ b_d1)
{
    int i = blockIdx.x * blockDim.x + threadIdx.x;   // 524288
    int n = i >> 9, k = i & 511;
    float w = (n < HID) ? W_gc[k * HID + n] : W_d1[k * HID + (n - HID)];
    w *= 1024.0f;            // exact pow2 scale; keeps lo-split out of fp16 subnormals
    __half a = __float2half_rn(w);
    float  r = w - __half2float(a);
    g_ws0[(size_t)n * K_DIM + k] = a;
    g_ws1[(size_t)n * K_DIM + k] = __float2half_rn(r);
    if (i < N_CAT) g_bias[i] = (i < HID) ? b_gc[i] : b_d1[i - HID];
}

// ---------------------------------------------------------------------------
// GEMM (round-8 structure, measured 1212us total): g_pre = (x @ (w0+w1)^T)
// * 2^-10 + bias with in-kernel fp16 split of x. CTA tile 256x256 (two
// 128x256 TMEM accumulators). KC=32, SW64, 3-stage combined A+B ring.
// A: LDG at loop TOP -> split/STS at loop BOTTOM. B: cp.async (issued before
// sts_a at the bottom for earlier L2 entry). Epilogue: paired LDTM.
// ---------------------------------------------------------------------------
#define GM 256
#define GN 256
#define KC 32
#define NCHUNK (K_DIM / KC)               /* 16 */
#define STAGE_BYTES 65536                 /* A0 16K | A1 16K | B0 16K | B1 16K */
#define GEMM_SMEM (1024 + 3 * STAGE_BYTES)

__global__ void __launch_bounds__(256, 1) gemm_kernel(const float* __restrict__ x)
{
    extern __shared__ char smem[];
    const int tid  = threadIdx.x;
    const int lane = tid & 31;
    const int wid  = tid >> 5;
    const size_t m0 = (size_t)blockIdx.y * GM;
    const int    n0 = blockIdx.x * GN;

#if defined(__CUDA_ARCH_FEAT_SM103_ALL)
    // ======================= tcgen05 path (sm_103a) =======================
    __shared__ __align__(16) uint32_t s_ctrl[8];  // [0]=tmem ptr; [2..7]=3 mbarriers
    char* tp = (char*)(((uintptr_t)smem + 1023) & ~(uintptr_t)1023);
    const uint32_t SAu   = smem_u32(tp);
    const uint32_t ctrl  = smem_u32(&s_ctrl[0]);
    const uint32_t mbar0 = smem_u32(&s_ctrl[2]);   // mbar[s] = mbar0 + 8*s

    if (wid == 0) tmem_alloc(ctrl, 512);
    if (tid == 0) {
        mbar_init(mbar0, 1);
        mbar_init(mbar0 + 8, 1);
        mbar_init(mbar0 + 16, 1);
    }
    __syncthreads();
    uint32_t tmem;
    asm volatile("ld.shared.b32 %0, [%1];" : "=r"(tmem) : "r"(ctrl));

    const uint32_t IDESC = (1u << 4) | ((GN / 8) << 17) | (8u << 24);   // M=128,N=256,f16

    auto load_b = [&](int c, int s) {                // B: 2048 x 16B via cp.async
        char* base = tp + s * STAGE_BYTES;
        #pragma unroll
        for (int i = 0; i < 8; i++) {
            int u = tid + 256 * i;
            int p = u >> 10, rem = u & 1023, row = rem >> 2, j = rem & 3;
            const __half* sbp = (p ? g_ws1 : g_ws0) + (size_t)(n0 + row) * K_DIM + c * KC + j * 8;
            cp16(smem_u32(base + 32768 + p * 16384 + sw64(row * 64 + j * 16)), sbp);
        }
        cp_commit();
    };

    auto ldg_a = [&](int c, float4* xr) {            // A fp32 -> registers (8 LDG.128)
        #pragma unroll
        for (int i = 0; i < 8; i++) {
            int u = tid + 256 * i;
            int row = u >> 3, jj = u & 7;
            xr[i] = *(const float4*)(x + (m0 + row) * K_DIM + c * KC + 4 * jj);
        }
    };
    auto sts_a = [&](int s, const float4* xr) {      // split + store to SW64 planes
        char* base = tp + s * STAGE_BYTES;
        #pragma unroll
        for (int i = 0; i < 8; i++) {
            int u = tid + 256 * i;
            int row = u >> 3, jj = u & 7;
            uint2 hi, lo;
            split4(xr[i], hi, lo);
            uint32_t off = sw64(row * 64 + jj * 8);
            *(uint2*)(base + off)         = hi;      // plane A0
            *(uint2*)(base + 16384 + off) = lo;      // plane A1
        }
    };

    // prologue: A chunks 0,1 staged; B chunks 0,1 in flight
    {
        float4 t0[8], t1[8];
        ldg_a(0, t0);
        ldg_a(1, t1);
        load_b(0, 0);
        load_b(1, 1);
        sts_a(0, t0);
        sts_a(1, t1);
    }

    #pragma unroll 1
    for (int c = 0; c < NCHUNK; c++) {
        float4 xr[8];
        if (c + 2 < NCHUNK) ldg_a(c + 2, xr);        // issue LDGs at top

        if (c + 1 < NCHUNK) cp_wait1(); else cp_wait0();   // B(c) landed
        fence_async_shared();
        __syncthreads();                              // A STS for chunk c visible

        if (wid == 0 && elect1()) {
            uint32_t sb = SAu + (c % 3) * STAGE_BYTES;
            #pragma unroll
            for (int ks = 0; ks < 2; ks++) {
                #pragma unroll
                for (int h = 0; h < 2; h++) {
                    uint64_t dA0 = mkdesc64(sb + h * 8192) + 2 * ks;
                    uint64_t dA1 = mkdesc64(sb + 16384 + h * 8192) + 2 * ks;
                    uint64_t dB0 = mkdesc64(sb + 32768) + 2 * ks;
                    uint64_t dB1 = mkdesc64(sb + 49152) + 2 * ks;
                    uint32_t d   = tmem + 256 * h;
                    uint32_t en  = (c == 0 && ks == 0) ? 0u : 1u;
                    mma_f16_ss(d, dA0, dB0, IDESC, en);
                    mma_f16_ss(d, dA0, dB1, IDESC, 1u);
                    mma_f16_ss(d, dA1, dB0, IDESC, 1u);
                }
            }
            mma_commit(mbar0 + 8 * (c % 3));
        }

        // drain chunk c-1: frees stage (c+2)%3 == (c-1)%3 for rewrite
        if (c >= 1) mbar_wait(mbar0 + 8 * ((c - 1) % 3), ((c - 1) / 3) & 1);

        if (c + 2 < NCHUNK) {
            load_b(c + 2, (c + 2) % 3);               // cp.async first: earlier L2 entry
            sts_a((c + 2) % 3, xr);                   // consume top LDGs
        }
    }
    mbar_wait(mbar0 + 8 * ((NCHUNK - 1) % 3), ((NCHUNK - 1) / 3) & 1);
    tcgen05_fence_after();

    // epilogue: warp w -> half h=w>>2 (rows m0+128h+32*(w&3)), cols 0..255
    // paired LDTM: two x32 loads per tcgen05.wait::ld
    {
        int h = wid >> 2, sub = wid & 3;
        size_t row = m0 + h * 128 + sub * 32 + lane;
        float* cp = g_pre + row * N_CAT + n0;
        const float sc = 1.0f / 1024.0f;
        #pragma unroll
        for (int cb = 0; cb < 8; cb += 2) {
            uint32_t r0[32], r1[32];
            LDTM_X32(r0, tmem + h * 256 + cb * 32);
            LDTM_X32(r1, tmem + h * 256 + cb * 32 + 32);
            tmem_wait_ld();
            #pragma unroll
            for (int j = 0; j < 32; j += 4) {
                float4 v;
                v.x = __uint_as_float(r0[j + 0]) * sc + g_bias[n0 + cb * 32 + j + 0];
                v.y = __uint_as_float(r0[j + 1]) * sc + g_bias[n0 + cb * 32 + j + 1];
                v.z = __uint_as_float(r0[j + 2]) * sc + g_bias[n0 + cb * 32 + j + 2];
                v.w = __uint_as_float(r0[j + 3]) * sc + g_bias[n0 + cb * 32 + j + 3];
                *(float4*)(cp + cb * 32 + j) = v;
            }
            #pragma unroll
            for (int j = 0; j < 32; j += 4) {
                float4 v;
                v.x = __uint_as_float(r1[j + 0]) * sc + g_bias[n0 + (cb + 1) * 32 + j + 0];
                v.y = __uint_as_float(r1[j + 1]) * sc + g_bias[n0 + (cb + 1) * 32 + j + 1];
                v.z = __uint_as_float(r1[j + 2]) * sc + g_bias[n0 + (cb + 1) * 32 + j + 2];
                v.w = __uint_as_float(r1[j + 3]) * sc + g_bias[n0 + (cb + 1) * 32 + j + 3];
                *(float4*)(cp + (cb + 1) * 32 + j) = v;
            }
        }
    }
    __syncthreads();
    if (wid == 0) tmem_dealloc(tmem, 512);

#else
    // ========= HMMA fallback (compute_103): four 128x128 sub-tiles =========
    const uint32_t sb = smem_u32(smem);
    const int wm = (wid >> 2) * 64;
    const int wn = (wid & 3) * 32;
    #define ROWB 80
    #define SPL_BYTES (128 * ROWB)
    #define HSTAGE (4 * SPL_BYTES)

    #pragma unroll 1
    for (int mh = 0; mh < 2; mh++) {
        const size_t m0h = m0 + 128 * mh;
        #pragma unroll 1
        for (int nh = 0; nh < 2; nh++) {
            const int n0h = n0 + 128 * nh;

            float c[4][4][4];
            #pragma unroll
            for (int i = 0; i < 4; i++)
                #pragma unroll
                for (int j = 0; j < 4; j++)
                    #pragma unroll
                    for (int k = 0; k < 4; k++) c[i][j][k] = 0.f;

            auto load_stage = [&](int cc, int st) {
                char* basep = smem + st * HSTAGE;
                uint32_t base = sb + st * HSTAGE;
                #pragma unroll
                for (int i = 0; i < 4; i++) {
                    int u = tid + 256 * i;
                    int r = u >> 3, jj = u & 7;
                    float4 xv = *(const float4*)(x + (m0h + r) * K_DIM + cc * 32 + 4 * jj);
                    uint2 hi, lo;
                    split4(xv, hi, lo);
                    *(uint2*)(basep + r * ROWB + jj * 8)             = hi;
                    *(uint2*)(basep + SPL_BYTES + r * ROWB + jj * 8) = lo;
                }
                #pragma unroll
                for (int i = 0; i < 4; i++) {
                    int u = tid + 256 * i;
                    int p = u >> 9, r = (u >> 2) & 127, j = u & 3;
                    const __half* src = (p ? g_ws1 : g_ws0) + (size_t)(n0h + r) * K_DIM + cc * 32 + j * 8;
                    cp16(base + 2 * SPL_BYTES + p * SPL_BYTES + r * ROWB + j * 16, src);
                }
                cp_commit();
            };

            auto compute_stage = [&](int st) {
                uint32_t Ab = sb + st * HSTAGE;
                uint32_t Bb = Ab + 2 * SPL_BYTES;
                #pragma unroll
                for (int kk = 0; kk < 2; kk++) {
                    uint32_t a[2][4][4];
                    uint32_t b[2][4][2];
                    #pragma unroll
                    for (int p = 0; p < 2; p++)
                        #pragma unroll
                        for (int mi = 0; mi < 4; mi++) {
                            uint32_t addr = Ab + p * SPL_BYTES
                                          + (wm + 16 * mi + (lane & 15)) * ROWB
                                          + kk * 32 + (lane >> 4) * 16;
                            ldsm4(a[p][mi], addr);
                        }
                    #pragma unroll
                    for (int p = 0; p < 2; p++)
                        #pragma unroll
                        for (int jj = 0; jj < 2; jj++) {
                            uint32_t nr = wn + 16 * jj + ((lane >> 4) & 1) * 8 + (lane & 7);
                            uint32_t addr = Bb + p * SPL_BYTES + nr * ROWB
                                          + kk * 32 + ((lane >> 3) & 1) * 16;
                            uint32_t r4[4];
                            ldsm4(r4, addr);
                            b[p][2 * jj][0]     = r4[0]; b[p][2 * jj][1]     = r4[1];
                            b[p][2 * jj + 1][0] = r4[2]; b[p][2 * jj + 1][1] = r4[3];
                        }
                    #pragma unroll
                    for (int mi = 0; mi < 4; mi++)
                        #pragma unroll
                        for (int nj = 0; nj < 4; nj++) {
                            mma16816(c[mi][nj], a[0][mi], b[0][nj]);
                            mma16816(c[mi][nj], a[0][mi], b[1][nj]);
                            mma16816(c[mi][nj], a[1][mi], b[0][nj]);
                        }
                }
            };

            load_stage(0, 0);
            #pragma unroll 1
            for (int cc = 0; cc < K_DIM / 32; cc++) {
                cp_wait0();
                __syncthreads();
                if (cc + 1 < K_DIM / 32) load_stage(cc + 1, (cc + 1) & 1);
                compute_stage(cc & 1);
            }
            __syncthreads();

            const float sc = 1.0f / 1024.0f;
            const int g = lane >> 2, t4 = lane & 3;
            #pragma unroll
            for (int mi = 0; mi < 4; mi++) {
                #pragma unroll
                for (int nj = 0; nj < 4; nj++) {
                    int col = n0h + wn + 8 * nj + t4 * 2;
                    float b0 = g_bias[col], b1 = g_bias[col + 1];
                    size_t row = m0h + wm + 16 * mi + g;
                    float2 v0 = {c[mi][nj][0] * sc + b0, c[mi][nj][1] * sc + b1};
                    *(float2*)(g_pre + row * N_CAT + col) = v0;
                    float2 v1 = {c[mi][nj][2] * sc + b0, c[mi][nj][3] * sc + b1};
                    *(float2*)(g_pre + (row + 8) * N_CAT + col) = v1;
                }
            }
        }
    }
    #undef ROWB
    #undef SPL_BYTES
    #undef HSTAGE
#endif
}

// ---------------------------------------------------------------------------
// Recurrence: one WARP per batch row, warp-synchronous (no smem, no barriers).
// Lane l owns neurons j = 128m + 4l + q (m,q in 0..3).  [measured 247us]
// ---------------------------------------------------------------------------
__global__ void __launch_bounds__(128) recur_kernel(
    const float* __restrict__ W_pc, const float* __restrict__ b_pc,
    const float* __restrict__ W_d1, const float* __restrict__ W_d2,
    const float* __restrict__ b_d2, float* __restrict__ out)
{
    const int wid  = threadIdx.x >> 5;
    const int l    = threadIdx.x & 31;
    const int r    = blockIdx.x * 4 + wid;      // batch row

    float m1[16], m2[16], m3[16];
    #pragma unroll
    for (int i = 0; i < 16; i++) { m1[i] = 0.f; m2[i] = 0.f; m3[i] = 0.f; }
    float oacc[OUT_N] = {0.f, 0.f, 0.f, 0.f, 0.f, 0.f, 0.f};

    for (int t = 0; t < T_STEPS; t++) {
        const float* pre = g_pre + ((size_t)t * B_ROWS + r) * N_CAT;
        unsigned bal[16];

        // ---- LIF1 (input = precomputed x@W_gc + b_gc) ----
        #pragma unroll
        for (int m = 0; m < 4; m++) {
            float4 p = *(const float4*)(pre + 128 * m + 4 * l);
            float pv[4] = {p.x, p.y, p.z, p.w};
            #pragma unroll
            for (int q = 0; q < 4; q++) {
                float v = 0.5f * (m1[4 * m + q] + pv[q]);
                bool  s = v > 1.0f;
                m1[4 * m + q] = s ? 0.f : v;
                bal[4 * m + q] = __ballot_sync(0xffffffffu, s);
            }
        }

        // ---- pc_pre = gc @ W_pc + b_pc (sparse row gather) ----
        float a2[16];
        #pragma unroll
        for (int m = 0; m < 4; m++) {
            float4 bv = *(const float4*)(b_pc + 128 * m + 4 * l);
            a2[4 * m + 0] = bv.x; a2[4 * m + 1] = bv.y;
            a2[4 * m + 2] = bv.z; a2[4 * m + 3] = bv.w;
        }
        #pragma unroll
        for (int mw = 0; mw < 16; mw++) {
            unsigned mm = bal[mw];
            while (mm) {
                int bit = __ffs(mm) - 1;
                mm &= mm - 1;
                int row2 = 128 * (mw >> 2) + 4 * bit + (mw & 3);
                const float* wr = W_pc + (size_t)row2 * HID;
                #pragma unroll
                for (int m = 0; m < 4; m++) {
                    float4 wv = *(const float4*)(wr + 128 * m + 4 * l);
                    a2[4 * m + 0] += wv.x; a2[4 * m + 1] += wv.y;
                    a2[4 * m + 2] += wv.z; a2[4 * m + 3] += wv.w;
                }
            }
        }

        // ---- LIF2 ----
        #pragma unroll
        for (int i = 0; i < 16; i++) {
            float v = 0.5f * (m2[i] + a2[i]);
            bool  s = v > 1.0f;
            m2[i] = s ? 0.f : v;
            bal[i] = __ballot_sync(0xffffffffu, s);
        }

        // ---- d1_pre = precomputed x-part + pc @ W_d1_bottom ----
        float a3[16];
        #pragma unroll
        for (int m = 0; m < 4; m++) {
            float4 p = *(const float4*)(pre + HID + 128 * m + 4 * l);
            a3[4 * m + 0] = p.x; a3[4 * m + 1] = p.y;
            a3[4 * m + 2] = p.z; a3[4 * m + 3] = p.w;
        }
        #pragma unroll
        for (int mw = 0; mw < 16; mw++) {
            unsigned mm = bal[mw];
            while (mm) {
                int bit = __ffs(mm) - 1;
                mm &= mm - 1;
                int row2 = HID + 128 * (mw >> 2) + 4 * bit + (mw & 3);
                const float* wr = W_d1 + (size_t)row2 * HID;
                #pragma unroll
                for (int m = 0; m < 4; m++) {
                    float4 wv = *(const float4*)(wr + 128 * m + 4 * l);
                    a3[4 * m + 0] += wv.x; a3[4 * m + 1] += wv.y;
                    a3[4 * m + 2] += wv.z; a3[4 * m + 3] += wv.w;
                }
            }
        }

        // ---- LIF3 -> readout ----
        #pragma unroll
        for (int i = 0; i < 16; i++) {
            float v = 0.5f * (m3[i] + a3[i]);
            bool  s = v > 1.0f;
            m3[i] = s ? 0.f : v;
            if (s) {
                int j = 128 * (i >> 2) + 4 * l + (i & 3);
                const float* wr = W_d2 + (size_t)j * OUT_N;
                #pragma unroll
                for (int o = 0; o < OUT_N; o++) oacc[o] += wr[o];
            }
        }
    }

    // ---- warp reduction of 7 outputs ----
    #pragma unroll
    for (int o = 0; o < OUT_N; o++) {
        float v = oacc[o];
        #pragma unroll
        for (int off = 16; off; off >>= 1) v += __shfl_down_sync(0xffffffffu, v, off);
        if (l == 0) out[(size_t)r * OUT_N + o] = v * (1.0f / (float)T_STEPS) + b_d2[o];
    }
}

// ---------------------------------------------------------------------------
extern "C" void kernel_launch(void* const* d_in, const int* in_sizes, int n_in,
                              void* d_out, int out_size)
{
    const float* x    = (const float*)d_in[0];
    const float* W_gc = (const float*)d_in[1];
    const float* b_gc = (const float*)d_in[2];
    const float* W_pc = (const float*)d_in[3];
    const float* b_pc = (const float*)d_in[4];
    const float* W_d1 = (const float*)d_in[5];
    const float* b_d1 = (const float*)d_in[6];
    const float* W_d2 = (const float*)d_in[7];
    const float* b_d2 = (const float*)d_in[8];
    float* out = (float*)d_out;
    (void)in_sizes; (void)n_in; (void)out_size;

    cudaFuncSetAttribute(gemm_kernel, cudaFuncAttributeMaxDynamicSharedMemorySize, GEMM_SMEM);

    convert_w_kernel<<<(N_CAT * K_DIM) / 256, 256>>>(W_gc, W_d1, b_gc, b_d1);

    dim3 grid(N_CAT / GN, M_TOT / GM);   // (4, 2048); x fastest -> A tiles reuse L2
    gemm_kernel<<<grid, 256, GEMM_SMEM>>>(x);

    recur_kernel<<<B_ROWS / 4, 128>>>(W_pc, b_pc, W_d1, W_d2, b_d2, out);
}

// round 16
// speedup vs baseline: 1.2447x; 1.0506x over previous
#include <cuda_runtime.h>
#include <cuda_fp16.h>
#include <cstdint>
#include <cstddef>

#define T_STEPS 16
#define B_ROWS  16384
#define HID     512
#define OUT_N   7
#define M_TOT   (T_STEPS * B_ROWS)   /* 262144 */
#define N_CAT   1024
#define K_DIM   512

// ---------------------------------------------------------------------------
// Static device scratch (no runtime allocation)
// ---------------------------------------------------------------------------
__device__ float  g_pre[(size_t)M_TOT * N_CAT];     // [T*B, 1024] pre-activations
__device__ __half g_ws0[(size_t)N_CAT * K_DIM];     // (1024*W)^T hi split, [N,K]
__device__ __half g_ws1[(size_t)N_CAT * K_DIM];     // (1024*W)^T lo split
__device__ float  g_bias[N_CAT];

// ---------------------------------------------------------------------------
// Helpers — baseline PTX (sm_80+, valid in every compilation pass)
// ---------------------------------------------------------------------------
__device__ __forceinline__ uint32_t smem_u32(const void* p) {
    uint32_t a;
    asm("{ .reg .u64 t; cvta.to.shared.u64 t, %1; cvt.u32.u64 %0, t; }" : "=r"(a) : "l"(p));
    return a;
}
__device__ __forceinline__ void cp16(uint32_t dst, const void* src) {
    asm volatile("cp.async.cg.shared.global [%0], [%1], 16;" :: "r"(dst), "l"(src) : "memory");
}
__device__ __forceinline__ void cp_commit() {
    asm volatile("cp.async.commit_group;" ::: "memory");
}
__device__ __forceinline__ void cp_wait0() {
    asm volatile("cp.async.wait_group 0;" ::: "memory");
}
__device__ __forceinline__ void cp_wait1() {
    asm volatile("cp.async.wait_group 1;" ::: "memory");
}
__device__ __forceinline__ void ldsm4(uint32_t* r, uint32_t addr) {
    asm volatile("ldmatrix.sync.aligned.m8n8.x4.shared.b16 {%0,%1,%2,%3}, [%4];"
                 : "=r"(r[0]), "=r"(r[1]), "=r"(r[2]), "=r"(r[3]) : "r"(addr));
}
__device__ __forceinline__ void mma16816(float* c, const uint32_t* a, const uint32_t* b) {
    asm volatile("mma.sync.aligned.m16n8k16.row.col.f32.f16.f16.f32 "
                 "{%0,%1,%2,%3}, {%4,%5,%6,%7}, {%8,%9}, {%0,%1,%2,%3};"
                 : "+f"(c[0]), "+f"(c[1]), "+f"(c[2]), "+f"(c[3])
                 : "r"(a[0]), "r"(a[1]), "r"(a[2]), "r"(a[3]), "r"(b[0]), "r"(b[1]));
}
__device__ __forceinline__ uint32_t sw64(uint32_t off) {
    return off ^ ((off >> 3) & 0x30);
}
// split one float4 into hi/lo fp16 pairs (uint2 each)
__device__ __forceinline__ void split4(float4 v, uint2& hi, uint2& lo) {
    union { __half h[4]; uint2 u; } p0, p1;
    float f[4] = {v.x, v.y, v.z, v.w};
    #pragma unroll
    for (int k = 0; k < 4; k++) {
        __half a = __float2half_rn(f[k]);
        float  r = f[k] - __half2float(a);
        p0.h[k] = a;
        p1.h[k] = __float2half_rn(r);
    }
    hi = p0.u; lo = p1.u;
}

// ---------------------------------------------------------------------------
// Helpers — sm_103a-only (feature-guarded; absent from compute_103 PTX)
// ---------------------------------------------------------------------------
#if defined(__CUDA_ARCH_FEAT_SM103_ALL)
__device__ __forceinline__ bool elect1() {
    uint32_t p;
    asm volatile("{ .reg .pred P; elect.sync _|P, 0xFFFFFFFF; selp.b32 %0, 1, 0, P; }" : "=r"(p));
    return p != 0;
}
__device__ __forceinline__ void mbar_init(uint32_t mbar, uint32_t cnt) {
    asm volatile("mbarrier.init.shared.b64 [%0], %1;" :: "r"(mbar), "r"(cnt) : "memory");
}
__device__ __forceinline__ void mbar_wait(uint32_t mbar, uint32_t parity) {
    asm volatile(
        "{\n\t.reg .pred P;\n\t"
        "LW_%=:\n\t"
        "mbarrier.try_wait.parity.acquire.cta.shared::cta.b64 P, [%0], %1, 0x989680;\n\t"
        "@P bra.uni LD_%=;\n\t"
        "bra.uni LW_%=;\n\t"
        "LD_%=:\n\t}"
        :: "r"(mbar), "r"(parity) : "memory");
}
__device__ __forceinline__ void tmem_alloc(uint32_t dst_smem, uint32_t ncols) {
    asm volatile("tcgen05.alloc.cta_group::1.sync.aligned.shared::cta.b32 [%0], %1;"
                 :: "r"(dst_smem), "r"(ncols) : "memory");
}
__device__ __forceinline__ void tmem_dealloc(uint32_t tmem, uint32_t ncols) {
    asm volatile("tcgen05.relinquish_alloc_permit.cta_group::1.sync.aligned;" ::: "memory");
    asm volatile("tcgen05.dealloc.cta_group::1.sync.aligned.b32 %0, %1;" :: "r"(tmem), "r"(ncols));
}
__device__ __forceinline__ void mma_f16_ss(uint32_t d, uint64_t ad, uint64_t bd,
                                           uint32_t idesc, uint32_t en) {
    asm volatile(
        "{\n\t.reg .pred p;\n\t"
        "setp.ne.u32 p, %4, 0;\n\t"
        "tcgen05.mma.cta_group::1.kind::f16 [%0], %1, %2, %3, {%5, %5, %5, %5}, p;\n\t}"
        :: "r"(d), "l"(ad), "l"(bd), "r"(idesc), "r"(en), "r"(0u) : "memory");
}
__device__ __forceinline__ void mma_commit(uint32_t mbar) {
    asm volatile("tcgen05.commit.cta_group::1.mbarrier::arrive::one.shared::cluster.b64 [%0];"
                 :: "r"(mbar) : "memory");
}
__device__ __forceinline__ void fence_async_shared() {
    asm volatile("fence.proxy.async.shared::cta;" ::: "memory");
}
__device__ __forceinline__ void tcgen05_fence_after() {
    asm volatile("tcgen05.fence::after_thread_sync;" ::: "memory");
}
__device__ __forceinline__ void tmem_wait_ld() {
    asm volatile("tcgen05.wait::ld.sync.aligned;" ::: "memory");
}
#define LDTM_X32(r, addr) \
    asm volatile( \
        "tcgen05.ld.sync.aligned.32x32b.x32.b32 " \
        "{%0, %1, %2, %3, %4, %5, %6, %7, " \
        " %8, %9, %10, %11, %12, %13, %14, %15, " \
        " %16, %17, %18, %19, %20, %21, %22, %23, " \
        " %24, %25, %26, %27, %28, %29, %30, %31}, [%32];" \
        : "=r"((r)[0]),  "=r"((r)[1]),  "=r"((r)[2]),  "=r"((r)[3]), \
          "=r"((r)[4]),  "=r"((r)[5]),  "=r"((r)[6]),  "=r"((r)[7]), \
          "=r"((r)[8]),  "=r"((r)[9]),  "=r"((r)[10]), "=r"((r)[11]), \
          "=r"((r)[12]), "=r"((r)[13]), "=r"((r)[14]), "=r"((r)[15]), \
          "=r"((r)[16]), "=r"((r)[17]), "=r"((r)[18]), "=r"((r)[19]), \
          "=r"((r)[20]), "=r"((r)[21]), "=r"((r)[22]), "=r"((r)[23]), \
          "=r"((r)[24]), "=r"((r)[25]), "=r"((r)[26]), "=r"((r)[27]), \
          "=r"((r)[28]), "=r"((r)[29]), "=r"((r)[30]), "=r"((r)[31]) \
        : "r"(addr))

// SW64 K-major descriptor: layout=4, version=1 (Blackwell), SBO=32, LBO=1.
static constexpr uint64_t DESC_BASE_SW64 =
    (4ULL << 61) | (1ULL << 46) | (32ULL << 32) | (1ULL << 16);
__device__ __forceinline__ uint64_t mkdesc64(uint32_t base) {
    return DESC_BASE_SW64 | (uint64_t)((base >> 4) & 0x3FFF);
}
#endif  // __CUDA_ARCH_FEAT_SM103_ALL

// ---------------------------------------------------------------------------
// Weight split conversion (2 MB — stays a tiny standalone kernel)
// ---------------------------------------------------------------------------
__global__ void convert_w_kernel(const float* __restrict__ W_gc, const float* __restrict__ W_d1,
                                 const float* __restrict__ b_gc, const float* __restrict__ b_d1)
{
    int i = blockIdx.x * blockDim.x + threadIdx.x;   // 524288
    int n = i >> 9, k = i & 511;
    float w = (n < HID) ? W_gc[k * HID + n] : W_d1[k * HID + (n - HID)];
    w *= 1024.0f;            // exact pow2 scale; keeps lo-split out of fp16 subnormals
    __half a = __float2half_rn(w);
    float  r = w - __half2float(a);
    g_ws0[(size_t)n * K_DIM + k] = a;
    g_ws1[(size_t)n * K_DIM + k] = __float2half_rn(r);
    if (i < N_CAT) g_bias[i] = (i < HID) ? b_gc[i] : b_d1[i - HID];
}

// ---------------------------------------------------------------------------
// GEMM (round-8 structure, measured best): g_pre = (x @ (w0+w1)^T) * 2^-10
// + bias with in-kernel fp16 split of x. CTA tile 256x256 (two 128x256 TMEM
// accumulators). KC=32, SW64, 3-stage combined A+B ring. A: LDG top ->
// split/STS bottom. B: cp.async. Epilogue: paired LDTM.
// ---------------------------------------------------------------------------
#define GM 256
#define GN 256
#define KC 32
#define NCHUNK (K_DIM / KC)               /* 16 */
#define STAGE_BYTES 65536                 /* A0 16K | A1 16K | B0 16K | B1 16K */
#define GEMM_SMEM (1024 + 3 * STAGE_BYTES)

__global__ void __launch_bounds__(256, 1) gemm_kernel(const float* __restrict__ x)
{
    extern __shared__ char smem[];
    const int tid  = threadIdx.x;
    const int lane = tid & 31;
    const int wid  = tid >> 5;
    const size_t m0 = (size_t)blockIdx.y * GM;
    const int    n0 = blockIdx.x * GN;

#if defined(__CUDA_ARCH_FEAT_SM103_ALL)
    // ======================= tcgen05 path (sm_103a) =======================
    __shared__ __align__(16) uint32_t s_ctrl[8];  // [0]=tmem ptr; [2..7]=3 mbarriers
    char* tp = (char*)(((uintptr_t)smem + 1023) & ~(uintptr_t)1023);
    const uint32_t SAu   = smem_u32(tp);
    const uint32_t ctrl  = smem_u32(&s_ctrl[0]);
    const uint32_t mbar0 = smem_u32(&s_ctrl[2]);   // mbar[s] = mbar0 + 8*s

    if (wid == 0) tmem_alloc(ctrl, 512);
    if (tid == 0) {
        mbar_init(mbar0, 1);
        mbar_init(mbar0 + 8, 1);
        mbar_init(mbar0 + 16, 1);
    }
    __syncthreads();
    uint32_t tmem;
    asm volatile("ld.shared.b32 %0, [%1];" : "=r"(tmem) : "r"(ctrl));

    const uint32_t IDESC = (1u << 4) | ((GN / 8) << 17) | (8u << 24);   // M=128,N=256,f16

    auto load_b = [&](int c, int s) {                // B: 2048 x 16B via cp.async
        char* base = tp + s * STAGE_BYTES;
        #pragma unroll
        for (int i = 0; i < 8; i++) {
            int u = tid + 256 * i;
            int p = u >> 10, rem = u & 1023, row = rem >> 2, j = rem & 3;
            const __half* sbp = (p ? g_ws1 : g_ws0) + (size_t)(n0 + row) * K_DIM + c * KC + j * 8;
            cp16(smem_u32(base + 32768 + p * 16384 + sw64(row * 64 + j * 16)), sbp);
        }
        cp_commit();
    };

    auto ldg_a = [&](int c, float4* xr) {            // A fp32 -> registers (8 LDG.128)
        #pragma unroll
        for (int i = 0; i < 8; i++) {
            int u = tid + 256 * i;
            int row = u >> 3, jj = u & 7;
            xr[i] = *(const float4*)(x + (m0 + row) * K_DIM + c * KC + 4 * jj);
        }
    };
    auto sts_a = [&](int s, const float4* xr) {      // split + store to SW64 planes
        char* base = tp + s * STAGE_BYTES;
        #pragma unroll
        for (int i = 0; i < 8; i++) {
            int u = tid + 256 * i;
            int row = u >> 3, jj = u & 7;
            uint2 hi, lo;
            split4(xr[i], hi, lo);
            uint32_t off = sw64(row * 64 + jj * 8);
            *(uint2*)(base + off)         = hi;      // plane A0
            *(uint2*)(base + 16384 + off) = lo;      // plane A1
        }
    };

    // prologue: A chunks 0,1 staged; B chunks 0,1 in flight
    {
        float4 t0[8], t1[8];
        ldg_a(0, t0);
        ldg_a(1, t1);
        load_b(0, 0);
        load_b(1, 1);
        sts_a(0, t0);
        sts_a(1, t1);
    }

    #pragma unroll 1
    for (int c = 0; c < NCHUNK; c++) {
        float4 xr[8];
        if (c + 2 < NCHUNK) ldg_a(c + 2, xr);        // issue LDGs at top

        if (c + 1 < NCHUNK) cp_wait1(); else cp_wait0();   // B(c) landed
        fence_async_shared();
        __syncthreads();                              // A STS for chunk c visible

        if (wid == 0 && elect1()) {
            uint32_t sb = SAu + (c % 3) * STAGE_BYTES;
            #pragma unroll
            for (int ks = 0; ks < 2; ks++) {
                #pragma unroll
                for (int h = 0; h < 2; h++) {
                    uint64_t dA0 = mkdesc64(sb + h * 8192) + 2 * ks;
                    uint64_t dA1 = mkdesc64(sb + 16384 + h * 8192) + 2 * ks;
                    uint64_t dB0 = mkdesc64(sb + 32768) + 2 * ks;
                    uint64_t dB1 = mkdesc64(sb + 49152) + 2 * ks;
                    uint32_t d   = tmem + 256 * h;
                    uint32_t en  = (c == 0 && ks == 0) ? 0u : 1u;
                    mma_f16_ss(d, dA0, dB0, IDESC, en);
                    mma_f16_ss(d, dA0, dB1, IDESC, 1u);
                    mma_f16_ss(d, dA1, dB0, IDESC, 1u);
                }
            }
            mma_commit(mbar0 + 8 * (c % 3));
        }

        // drain chunk c-1: frees stage (c+2)%3 == (c-1)%3 for rewrite
        if (c >= 1) mbar_wait(mbar0 + 8 * ((c - 1) % 3), ((c - 1) / 3) & 1);

        if (c + 2 < NCHUNK) {
            load_b(c + 2, (c + 2) % 3);               // cp.async first: earlier L2 entry
            sts_a((c + 2) % 3, xr);                   // consume top LDGs
        }
    }
    mbar_wait(mbar0 + 8 * ((NCHUNK - 1) % 3), ((NCHUNK - 1) / 3) & 1);
    tcgen05_fence_after();

    // epilogue: warp w -> half h=w>>2 (rows m0+128h+32*(w&3)), cols 0..255
    // paired LDTM: two x32 loads per tcgen05.wait::ld
    {
        int h = wid >> 2, sub = wid & 3;
        size_t row = m0 + h * 128 + sub * 32 + lane;
        float* cp = g_pre + row * N_CAT + n0;
        const float sc = 1.0f / 1024.0f;
        #pragma unroll
        for (int cb = 0; cb < 8; cb += 2) {
            uint32_t r0[32], r1[32];
            LDTM_X32(r0, tmem + h * 256 + cb * 32);
            LDTM_X32(r1, tmem + h * 256 + cb * 32 + 32);
            tmem_wait_ld();
            #pragma unroll
            for (int j = 0; j < 32; j += 4) {
                float4 v;
                v.x = __uint_as_float(r0[j + 0]) * sc + g_bias[n0 + cb * 32 + j + 0];
                v.y = __uint_as_float(r0[j + 1]) * sc + g_bias[n0 + cb * 32 + j + 1];
                v.z = __uint_as_float(r0[j + 2]) * sc + g_bias[n0 + cb * 32 + j + 2];
                v.w = __uint_as_float(r0[j + 3]) * sc + g_bias[n0 + cb * 32 + j + 3];
                *(float4*)(cp + cb * 32 + j) = v;
            }
            #pragma unroll
            for (int j = 0; j < 32; j += 4) {
                float4 v;
                v.x = __uint_as_float(r1[j + 0]) * sc + g_bias[n0 + (cb + 1) * 32 + j + 0];
                v.y = __uint_as_float(r1[j + 1]) * sc + g_bias[n0 + (cb + 1) * 32 + j + 1];
                v.z = __uint_as_float(r1[j + 2]) * sc + g_bias[n0 + (cb + 1) * 32 + j + 2];
                v.w = __uint_as_float(r1[j + 3]) * sc + g_bias[n0 + (cb + 1) * 32 + j + 3];
                *(float4*)(cp + (cb + 1) * 32 + j) = v;
            }
        }
    }
    __syncthreads();
    if (wid == 0) tmem_dealloc(tmem, 512);

#else
    // ========= HMMA fallback (compute_103): four 128x128 sub-tiles =========
    const uint32_t sb = smem_u32(smem);
    const int wm = (wid >> 2) * 64;
    const int wn = (wid & 3) * 32;
    #define ROWB 80
    #define SPL_BYTES (128 * ROWB)
    #define HSTAGE (4 * SPL_BYTES)

    #pragma unroll 1
    for (int mh = 0; mh < 2; mh++) {
        const size_t m0h = m0 + 128 * mh;
        #pragma unroll 1
        for (int nh = 0; nh < 2; nh++) {
            const int n0h = n0 + 128 * nh;

            float c[4][4][4];
            #pragma unroll
            for (int i = 0; i < 4; i++)
                #pragma unroll
                for (int j = 0; j < 4; j++)
                    #pragma unroll
                    for (int k = 0; k < 4; k++) c[i][j][k] = 0.f;

            auto load_stage = [&](int cc, int st) {
                char* basep = smem + st * HSTAGE;
                uint32_t base = sb + st * HSTAGE;
                #pragma unroll
                for (int i = 0; i < 4; i++) {
                    int u = tid + 256 * i;
                    int r = u >> 3, jj = u & 7;
                    float4 xv = *(const float4*)(x + (m0h + r) * K_DIM + cc * 32 + 4 * jj);
                    uint2 hi, lo;
                    split4(xv, hi, lo);
                    *(uint2*)(basep + r * ROWB + jj * 8)             = hi;
                    *(uint2*)(basep + SPL_BYTES + r * ROWB + jj * 8) = lo;
                }
                #pragma unroll
                for (int i = 0; i < 4; i++) {
                    int u = tid + 256 * i;
                    int p = u >> 9, r = (u >> 2) & 127, j = u & 3;
                    const __half* src = (p ? g_ws1 : g_ws0) + (size_t)(n0h + r) * K_DIM + cc * 32 + j * 8;
                    cp16(base + 2 * SPL_BYTES + p * SPL_BYTES + r * ROWB + j * 16, src);
                }
                cp_commit();
            };

            auto compute_stage = [&](int st) {
                uint32_t Ab = sb + st * HSTAGE;
                uint32_t Bb = Ab + 2 * SPL_BYTES;
                #pragma unroll
                for (int kk = 0; kk < 2; kk++) {
                    uint32_t a[2][4][4];
                    uint32_t b[2][4][2];
                    #pragma unroll
                    for (int p = 0; p < 2; p++)
                        #pragma unroll
                        for (int mi = 0; mi < 4; mi++) {
                            uint32_t addr = Ab + p * SPL_BYTES
                                          + (wm + 16 * mi + (lane & 15)) * ROWB
                                          + kk * 32 + (lane >> 4) * 16;
                            ldsm4(a[p][mi], addr);
                        }
                    #pragma unroll
                    for (int p = 0; p < 2; p++)
                        #pragma unroll
                        for (int jj = 0; jj < 2; jj++) {
                            uint32_t nr = wn + 16 * jj + ((lane >> 4) & 1) * 8 + (lane & 7);
                            uint32_t addr = Bb + p * SPL_BYTES + nr * ROWB
                                          + kk * 32 + ((lane >> 3) & 1) * 16;
                            uint32_t r4[4];
                            ldsm4(r4, addr);
                            b[p][2 * jj][0]     = r4[0]; b[p][2 * jj][1]     = r4[1];
                            b[p][2 * jj + 1][0] = r4[2]; b[p][2 * jj + 1][1] = r4[3];
                        }
                    #pragma unroll
                    for (int mi = 0; mi < 4; mi++)
                        #pragma unroll
                        for (int nj = 0; nj < 4; nj++) {
                            mma16816(c[mi][nj], a[0][mi], b[0][nj]);
                            mma16816(c[mi][nj], a[0][mi], b[1][nj]);
                            mma16816(c[mi][nj], a[1][mi], b[0][nj]);
                        }
                }
            };

            load_stage(0, 0);
            #pragma unroll 1
            for (int cc = 0; cc < K_DIM / 32; cc++) {
                cp_wait0();
                __syncthreads();
                if (cc + 1 < K_DIM / 32) load_stage(cc + 1, (cc + 1) & 1);
                compute_stage(cc & 1);
            }
            __syncthreads();

            const float sc = 1.0f / 1024.0f;
            const int g = lane >> 2, t4 = lane & 3;
            #pragma unroll
            for (int mi = 0; mi < 4; mi++) {
                #pragma unroll
                for (int nj = 0; nj < 4; nj++) {
                    int col = n0h + wn + 8 * nj + t4 * 2;
                    float b0 = g_bias[col], b1 = g_bias[col + 1];
                    size_t row = m0h + wm + 16 * mi + g;
                    float2 v0 = {c[mi][nj][0] * sc + b0, c[mi][nj][1] * sc + b1};
                    *(float2*)(g_pre + row * N_CAT + col) = v0;
                    float2 v1 = {c[mi][nj][2] * sc + b0, c[mi][nj][3] * sc + b1};
                    *(float2*)(g_pre + (row + 8) * N_CAT + col) = v1;
                }
            }
        }
    }
    #undef ROWB
    #undef SPL_BYTES
    #undef HSTAGE
#endif
}

// ---------------------------------------------------------------------------
// Recurrence: one WARP per batch row, warp-synchronous. Lane l owns neurons
// j = 128m + 4l + q. Both pre halves loaded at step top (8 concurrent
// LDG.128); gather scans skipped entirely when no neuron spiked (uniform
// branch — ballot words are warp-uniform; ~96% of layer-steps are empty).
// ---------------------------------------------------------------------------
__global__ void __launch_bounds__(128) recur_kernel(
    const float* __restrict__ W_pc, const float* __restrict__ b_pc,
    const float* __restrict__ W_d1, const float* __restrict__ W_d2,
    const float* __restrict__ b_d2, float* __restrict__ out)
{
    const int wid  = threadIdx.x >> 5;
    const int l    = threadIdx.x & 31;
    const int r    = blockIdx.x * 4 + wid;      // batch row

    float m1[16], m2[16], m3[16];
    #pragma unroll
    for (int i = 0; i < 16; i++) { m1[i] = 0.f; m2[i] = 0.f; m3[i] = 0.f; }
    float oacc[OUT_N] = {0.f, 0.f, 0.f, 0.f, 0.f, 0.f, 0.f};

    for (int t = 0; t < T_STEPS; t++) {
        const float* pre = g_pre + ((size_t)t * B_ROWS + r) * N_CAT;
        unsigned bal[16];

        // ---- load BOTH pre halves up front: 8 independent LDG.128 ----
        float4 pa[4], pb[4];
        #pragma unroll
        for (int m = 0; m < 4; m++) pa[m] = *(const float4*)(pre + 128 * m + 4 * l);
        #pragma unroll
        for (int m = 0; m < 4; m++) pb[m] = *(const float4*)(pre + HID + 128 * m + 4 * l);

        // ---- LIF1 (input = precomputed x@W_gc + b_gc) ----
        #pragma unroll
        for (int m = 0; m < 4; m++) {
            float pv[4] = {pa[m].x, pa[m].y, pa[m].z, pa[m].w};
            #pragma unroll
            for (int q = 0; q < 4; q++) {
                float v = 0.5f * (m1[4 * m + q] + pv[q]);
                bool  s = v > 1.0f;
                m1[4 * m + q] = s ? 0.f : v;
                bal[4 * m + q] = __ballot_sync(0xffffffffu, s);
            }
        }

        // ---- pc_pre = gc @ W_pc + b_pc (sparse row gather) ----
        float a2[16];
        #pragma unroll
        for (int m = 0; m < 4; m++) {
            float4 bv = *(const float4*)(b_pc + 128 * m + 4 * l);
            a2[4 * m + 0] = bv.x; a2[4 * m + 1] = bv.y;
            a2[4 * m + 2] = bv.z; a2[4 * m + 3] = bv.w;
        }
        {
            unsigned any = 0;
            #pragma unroll
            for (int mw = 0; mw < 16; mw++) any |= bal[mw];
            if (any) {
                #pragma unroll
                for (int mw = 0; mw < 16; mw++) {
                    unsigned mm = bal[mw];
                    while (mm) {
                        int bit = __ffs(mm) - 1;
                        mm &= mm - 1;
                        int row2 = 128 * (mw >> 2) + 4 * bit + (mw & 3);
                        const float* wr = W_pc + (size_t)row2 * HID;
                        #pragma unroll
                        for (int m = 0; m < 4; m++) {
                            float4 wv = *(const float4*)(wr + 128 * m + 4 * l);
                            a2[4 * m + 0] += wv.x; a2[4 * m + 1] += wv.y;
                            a2[4 * m + 2] += wv.z; a2[4 * m + 3] += wv.w;
                        }
                    }
                }
            }
        }

        // ---- LIF2 ----
        #pragma unroll
        for (int i = 0; i < 16; i++) {
            float v = 0.5f * (m2[i] + a2[i]);
            bool  s = v > 1.0f;
            m2[i] = s ? 0.f : v;
            bal[i] = __ballot_sync(0xffffffffu, s);
        }

        // ---- d1_pre = precomputed x-part + pc @ W_d1_bottom ----
        float a3[16];
        #pragma unroll
        for (int m = 0; m < 4; m++) {
            a3[4 * m + 0] = pb[m].x; a3[4 * m + 1] = pb[m].y;
            a3[4 * m + 2] = pb[m].z; a3[4 * m + 3] = pb[m].w;
        }
        {
            unsigned any = 0;
            #pragma unroll
            for (int mw = 0; mw < 16; mw++) any |= bal[mw];
            if (any) {
                #pragma unroll
                for (int mw = 0; mw < 16; mw++) {
                    unsigned mm = bal[mw];
                    while (mm) {
                        int bit = __ffs(mm) - 1;
                        mm &= mm - 1;
                        int row2 = HID + 128 * (mw >> 2) + 4 * bit + (mw & 3);
                        const float* wr = W_d1 + (size_t)row2 * HID;
                        #pragma unroll
                        for (int m = 0; m < 4; m++) {
                            float4 wv = *(const float4*)(wr + 128 * m + 4 * l);
                            a3[4 * m + 0] += wv.x; a3[4 * m + 1] += wv.y;
                            a3[4 * m + 2] += wv.z; a3[4 * m + 3] += wv.w;
                        }
                    }
                }
            }
        }

        // ---- LIF3 -> readout ----
        #pragma unroll
        for (int i = 0; i < 16; i++) {
            float v = 0.5f * (m3[i] + a3[i]);
            bool  s = v > 1.0f;
            m3[i] = s ? 0.f : v;
            if (s) {
                int j = 128 * (i >> 2) + 4 * l + (i & 3);
                const float* wr = W_d2 + (size_t)j * OUT_N;
                #pragma unroll
                for (int o = 0; o < OUT_N; o++) oacc[o] += wr[o];
            }
        }
    }

    // ---- warp reduction of 7 outputs ----
    #pragma unroll
    for (int o = 0; o < OUT_N; o++) {
        float v = oacc[o];
        #pragma unroll
        for (int off = 16; off; off >>= 1) v += __shfl_down_sync(0xffffffffu, v, off);
        if (l == 0) out[(size_t)r * OUT_N + o] = v * (1.0f / (float)T_STEPS) + b_d2[o];
    }
}

// ---------------------------------------------------------------------------
extern "C" void kernel_launch(void* const* d_in, const int* in_sizes, int n_in,
                              void* d_out, int out_size)
{
    const float* x    = (const float*)d_in[0];
    const float* W_gc = (const float*)d_in[1];
    const float* b_gc = (const float*)d_in[2];
    const float* W_pc = (const float*)d_in[3];
    const float* b_pc = (const float*)d_in[4];
    const float* W_d1 = (const float*)d_in[5];
    const float* b_d1 = (const float*)d_in[6];
    const float* W_d2 = (const float*)d_in[7];
    const float* b_d2 = (const float*)d_in[8];
    float* out = (float*)d_out;
    (void)in_sizes; (void)n_in; (void)out_size;

    cudaFuncSetAttribute(gemm_kernel, cudaFuncAttributeMaxDynamicSharedMemorySize, GEMM_SMEM);

    convert_w_kernel<<<(N_CAT * K_DIM) / 256, 256>>>(W_gc, W_d1, b_gc, b_d1);

    dim3 grid(N_CAT / GN, M_TOT / GM);   // (4, 2048); x fastest -> A tiles reuse L2
    gemm_kernel<<<grid, 256, GEMM_SMEM>>>(x);

    recur_kernel<<<B_ROWS / 4, 128>>>(W_pc, b_pc, W_d1, W_d2, b_d2, out);
}

// round 17
// speedup vs baseline: 1.2689x; 1.0194x over previous
#include <cuda_runtime.h>
#include <cuda_fp16.h>
#include <cstdint>
#include <cstddef>

#define T_STEPS 16
#define B_ROWS  16384
#define HID     512
#define OUT_N   7
#define M_TOT   (T_STEPS * B_ROWS)   /* 262144 */
#define N_CAT   1024
#define K_DIM   512
#define N_BB    64                    /* batch blocks of 256 rows */
#define LAG     3                     /* recur lags gemm by LAG b-blocks */
#define N_GCTA  4096                  /* gemm CTAs (64 per b-block) */
#define N_CTA   (N_GCTA + 64 * LAG)   /* + tail recur-only CTAs */

// ---------------------------------------------------------------------------
// Static device scratch (no runtime allocation)
// ---------------------------------------------------------------------------
__device__ float    g_pre[(size_t)M_TOT * N_CAT];   // [T*B, 1024] pre-activations
__device__ __half   g_ws0[(size_t)N_CAT * K_DIM];   // (1024*W)^T hi split, [N,K]
__device__ __half   g_ws1[(size_t)N_CAT * K_DIM];   // (1024*W)^T lo split
__device__ float    g_bias[N_CAT];
__device__ unsigned g_done[N_BB];                   // per-b-block completion counters

// ---------------------------------------------------------------------------
// Helpers — baseline PTX (sm_70+/sm_80+, valid in every compilation pass)
// ---------------------------------------------------------------------------
__device__ __forceinline__ uint32_t smem_u32(const void* p) {
    uint32_t a;
    asm("{ .reg .u64 t; cvta.to.shared.u64 t, %1; cvt.u32.u64 %0, t; }" : "=r"(a) : "l"(p));
    return a;
}
__device__ __forceinline__ void cp16(uint32_t dst, const void* src) {
    asm volatile("cp.async.cg.shared.global [%0], [%1], 16;" :: "r"(dst), "l"(src) : "memory");
}
__device__ __forceinline__ void cp_commit() {
    asm volatile("cp.async.commit_group;" ::: "memory");
}
__device__ __forceinline__ void cp_wait0() {
    asm volatile("cp.async.wait_group 0;" ::: "memory");
}
__device__ __forceinline__ void cp_wait1() {
    asm volatile("cp.async.wait_group 1;" ::: "memory");
}
__device__ __forceinline__ void ldsm4(uint32_t* r, uint32_t addr) {
    asm volatile("ldmatrix.sync.aligned.m8n8.x4.shared.b16 {%0,%1,%2,%3}, [%4];"
                 : "=r"(r[0]), "=r"(r[1]), "=r"(r[2]), "=r"(r[3]) : "r"(addr));
}
__device__ __forceinline__ void mma16816(float* c, const uint32_t* a, const uint32_t* b) {
    asm volatile("mma.sync.aligned.m16n8k16.row.col.f32.f16.f16.f32 "
                 "{%0,%1,%2,%3}, {%4,%5,%6,%7}, {%8,%9}, {%0,%1,%2,%3};"
                 : "+f"(c[0]), "+f"(c[1]), "+f"(c[2]), "+f"(c[3])
                 : "r"(a[0]), "r"(a[1]), "r"(a[2]), "r"(a[3]), "r"(b[0]), "r"(b[1]));
}
__device__ __forceinline__ uint32_t sw64(uint32_t off) {
    return off ^ ((off >> 3) & 0x30);
}
// barrier over the 256 GEMM threads only (warps 0-7); recur warps never join
#define BAR_GEMM() asm volatile("bar.sync 1, 256;" ::: "memory")

__device__ __forceinline__ unsigned poll_acq(const unsigned* p) {
    unsigned v;
    asm volatile("ld.acquire.gpu.global.u32 %0, [%1];" : "=r"(v) : "l"(p) : "memory");
    return v;
}
__device__ __forceinline__ void npause() {
    asm volatile("nanosleep.u32 200;");
}
// split one float4 into hi/lo fp16 pairs (uint2 each)
__device__ __forceinline__ void split4(float4 v, uint2& hi, uint2& lo) {
    union { __half h[4]; uint2 u; } p0, p1;
    float f[4] = {v.x, v.y, v.z, v.w};
    #pragma unroll
    for (int k = 0; k < 4; k++) {
        __half a = __float2half_rn(f[k]);
        float  r = f[k] - __half2float(a);
        p0.h[k] = a;
        p1.h[k] = __float2half_rn(r);
    }
    hi = p0.u; lo = p1.u;
}

// ---------------------------------------------------------------------------
// Helpers — sm_103a-only (feature-guarded; absent from compute_103 PTX)
// ---------------------------------------------------------------------------
#if defined(__CUDA_ARCH_FEAT_SM103_ALL)
__device__ __forceinline__ bool elect1() {
    uint32_t p;
    asm volatile("{ .reg .pred P; elect.sync _|P, 0xFFFFFFFF; selp.b32 %0, 1, 0, P; }" : "=r"(p));
    return p != 0;
}
__device__ __forceinline__ void mbar_init(uint32_t mbar, uint32_t cnt) {
    asm volatile("mbarrier.init.shared.b64 [%0], %1;" :: "r"(mbar), "r"(cnt) : "memory");
}
__device__ __forceinline__ void mbar_wait(uint32_t mbar, uint32_t parity) {
    asm volatile(
        "{\n\t.reg .pred P;\n\t"
        "LW_%=:\n\t"
        "mbarrier.try_wait.parity.acquire.cta.shared::cta.b64 P, [%0], %1, 0x989680;\n\t"
        "@P bra.uni LD_%=;\n\t"
        "bra.uni LW_%=;\n\t"
        "LD_%=:\n\t}"
        :: "r"(mbar), "r"(parity) : "memory");
}
__device__ __forceinline__ void tmem_alloc(uint32_t dst_smem, uint32_t ncols) {
    asm volatile("tcgen05.alloc.cta_group::1.sync.aligned.shared::cta.b32 [%0], %1;"
                 :: "r"(dst_smem), "r"(ncols) : "memory");
}
__device__ __forceinline__ void tmem_dealloc(uint32_t tmem, uint32_t ncols) {
    asm volatile("tcgen05.relinquish_alloc_permit.cta_group::1.sync.aligned;" ::: "memory");
    asm volatile("tcgen05.dealloc.cta_group::1.sync.aligned.b32 %0, %1;" :: "r"(tmem), "r"(ncols));
}
__device__ __forceinline__ void mma_f16_ss(uint32_t d, uint64_t ad, uint64_t bd,
                                           uint32_t idesc, uint32_t en) {
    asm volatile(
        "{\n\t.reg .pred p;\n\t"
        "setp.ne.u32 p, %4, 0;\n\t"
        "tcgen05.mma.cta_group::1.kind::f16 [%0], %1, %2, %3, {%5, %5, %5, %5}, p;\n\t}"
        :: "r"(d), "l"(ad), "l"(bd), "r"(idesc), "r"(en), "r"(0u) : "memory");
}
__device__ __forceinline__ void mma_commit(uint32_t mbar) {
    asm volatile("tcgen05.commit.cta_group::1.mbarrier::arrive::one.shared::cluster.b64 [%0];"
                 :: "r"(mbar) : "memory");
}
__device__ __forceinline__ void fence_async_shared() {
    asm volatile("fence.proxy.async.shared::cta;" ::: "memory");
}
__device__ __forceinline__ void tcgen05_fence_after() {
    asm volatile("tcgen05.fence::after_thread_sync;" ::: "memory");
}
__device__ __forceinline__ void tmem_wait_ld() {
    asm volatile("tcgen05.wait::ld.sync.aligned;" ::: "memory");
}
#define LDTM_X32(r, addr) \
    asm volatile( \
        "tcgen05.ld.sync.aligned.32x32b.x32.b32 " \
        "{%0, %1, %2, %3, %4, %5, %6, %7, " \
        " %8, %9, %10, %11, %12, %13, %14, %15, " \
        " %16, %17, %18, %19, %20, %21, %22, %23, " \
        " %24, %25, %26, %27, %28, %29, %30, %31}, [%32];" \
        : "=r"((r)[0]),  "=r"((r)[1]),  "=r"((r)[2]),  "=r"((r)[3]), \
          "=r"((r)[4]),  "=r"((r)[5]),  "=r"((r)[6]),  "=r"((r)[7]), \
          "=r"((r)[8]),  "=r"((r)[9]),  "=r"((r)[10]), "=r"((r)[11]), \
          "=r"((r)[12]), "=r"((r)[13]), "=r"((r)[14]), "=r"((r)[15]), \
          "=r"((r)[16]), "=r"((r)[17]), "=r"((r)[18]), "=r"((r)[19]), \
          "=r"((r)[20]), "=r"((r)[21]), "=r"((r)[22]), "=r"((r)[23]), \
          "=r"((r)[24]), "=r"((r)[25]), "=r"((r)[26]), "=r"((r)[27]), \
          "=r"((r)[28]), "=r"((r)[29]), "=r"((r)[30]), "=r"((r)[31]) \
        : "r"(addr))

// SW64 K-major descriptor: layout=4, version=1 (Blackwell), SBO=32, LBO=1.
static constexpr uint64_t DESC_BASE_SW64 =
    (4ULL << 61) | (1ULL << 46) | (32ULL << 32) | (1ULL << 16);
__device__ __forceinline__ uint64_t mkdesc64(uint32_t base) {
    return DESC_BASE_SW64 | (uint64_t)((base >> 4) & 0x3FFF);
}
#endif  // __CUDA_ARCH_FEAT_SM103_ALL

// ---------------------------------------------------------------------------
// Weight split conversion + flag reset (runs before the fused kernel)
// ---------------------------------------------------------------------------
__global__ void convert_w_kernel(const float* __restrict__ W_gc, const float* __restrict__ W_d1,
                                 const float* __restrict__ b_gc, const float* __restrict__ b_d1)
{
    int i = blockIdx.x * blockDim.x + threadIdx.x;   // 524288
    int n = i >> 9, k = i & 511;
    float w = (n < HID) ? W_gc[k * HID + n] : W_d1[k * HID + (n - HID)];
    w *= 1024.0f;            // exact pow2 scale; keeps lo-split out of fp16 subnormals
    __half a = __float2half_rn(w);
    float  r = w - __half2float(a);
    g_ws0[(size_t)n * K_DIM + k] = a;
    g_ws1[(size_t)n * K_DIM + k] = __float2half_rn(r);
    if (i < N_CAT) g_bias[i] = (i < HID) ? b_gc[i] : b_d1[i - HID];
    if (i < N_BB)  g_done[i] = 0;                    // reset per launch (graph replay safe)
}

// ---------------------------------------------------------------------------
// FUSED kernel, 384 threads/CTA:
//   warps 0-7  : measured-best tcgen05 GEMM tile (256x256), b-block-major
//                m-schedule; signals g_done[bb] on completion.
//   warps 8-11 : one rowgroup (4 batch rows) of the LIF recurrence, consuming
//                b-block (cid>>6 - LAG), which completed ~1.3 waves earlier.
// Grid: 4096 gemm CTAs + 192 tail recur-only CTAs.
// ---------------------------------------------------------------------------
#define GM 256
#define GN 256
#define KC 32
#define NCHUNK (K_DIM / KC)               /* 16 */
#define STAGE_BYTES 65536                 /* A0 16K | A1 16K | B0 16K | B1 16K */
#define GEMM_SMEM (1024 + 3 * STAGE_BYTES)

__global__ void __launch_bounds__(384, 1) fused_kernel(
    const float* __restrict__ x,
    const float* __restrict__ W_pc, const float* __restrict__ b_pc,
    const float* __restrict__ W_d1, const float* __restrict__ W_d2,
    const float* __restrict__ b_d2, float* __restrict__ out)
{
    extern __shared__ char smem[];
    const int cid  = blockIdx.x;
    const int tid  = threadIdx.x;
    const int lane = tid & 31;
    const int wid  = tid >> 5;

    if (tid < 256) {
        // ================== GEMM part (warps 0-7) ==================
        if (cid < N_GCTA) {
            const int nx = cid & 3, sy = cid >> 2;
            const int bb = sy >> 4, tt = sy & 15;
            const size_t m0 = (size_t)(tt * N_BB + bb) * GM;   // b-block-major m-tile
            const int    n0 = nx * GN;

#if defined(__CUDA_ARCH_FEAT_SM103_ALL)
            __shared__ __align__(16) uint32_t s_ctrl[8];
            char* tp = (char*)(((uintptr_t)smem + 1023) & ~(uintptr_t)1023);
            const uint32_t SAu   = smem_u32(tp);
            const uint32_t ctrl  = smem_u32(&s_ctrl[0]);
            const uint32_t mbar0 = smem_u32(&s_ctrl[2]);

            if (wid == 0) tmem_alloc(ctrl, 512);
            if (tid == 0) {
                mbar_init(mbar0, 1);
                mbar_init(mbar0 + 8, 1);
                mbar_init(mbar0 + 16, 1);
            }
            BAR_GEMM();
            uint32_t tmem;
            asm volatile("ld.shared.b32 %0, [%1];" : "=r"(tmem) : "r"(ctrl));

            const uint32_t IDESC = (1u << 4) | ((GN / 8) << 17) | (8u << 24);

            auto load_b = [&](int c, int s) {
                char* base = tp + s * STAGE_BYTES;
                #pragma unroll
                for (int i = 0; i < 8; i++) {
                    int u = tid + 256 * i;
                    int p = u >> 10, rem = u & 1023, row = rem >> 2, j = rem & 3;
                    const __half* sbp = (p ? g_ws1 : g_ws0) + (size_t)(n0 + row) * K_DIM + c * KC + j * 8;
                    cp16(smem_u32(base + 32768 + p * 16384 + sw64(row * 64 + j * 16)), sbp);
                }
                cp_commit();
            };
            auto ldg_a = [&](int c, float4* xr) {
                #pragma unroll
                for (int i = 0; i < 8; i++) {
                    int u = tid + 256 * i;
                    int row = u >> 3, jj = u & 7;
                    xr[i] = *(const float4*)(x + (m0 + row) * K_DIM + c * KC + 4 * jj);
                }
            };
            auto sts_a = [&](int s, const float4* xr) {
                char* base = tp + s * STAGE_BYTES;
                #pragma unroll
                for (int i = 0; i < 8; i++) {
                    int u = tid + 256 * i;
                    int row = u >> 3, jj = u & 7;
                    uint2 hi, lo;
                    split4(xr[i], hi, lo);
                    uint32_t off = sw64(row * 64 + jj * 8);
                    *(uint2*)(base + off)         = hi;
                    *(uint2*)(base + 16384 + off) = lo;
                }
            };

            {
                float4 t0[8], t1[8];
                ldg_a(0, t0);
                ldg_a(1, t1);
                load_b(0, 0);
                load_b(1, 1);
                sts_a(0, t0);
                sts_a(1, t1);
            }

            #pragma unroll 1
            for (int c = 0; c < NCHUNK; c++) {
                float4 xr[8];
                if (c + 2 < NCHUNK) ldg_a(c + 2, xr);

                if (c + 1 < NCHUNK) cp_wait1(); else cp_wait0();
                fence_async_shared();
                BAR_GEMM();

                if (wid == 0 && elect1()) {
                    uint32_t sb = SAu + (c % 3) * STAGE_BYTES;
                    #pragma unroll
                    for (int ks = 0; ks < 2; ks++) {
                        #pragma unroll
                        for (int h = 0; h < 2; h++) {
                            uint64_t dA0 = mkdesc64(sb + h * 8192) + 2 * ks;
                            uint64_t dA1 = mkdesc64(sb + 16384 + h * 8192) + 2 * ks;
                            uint64_t dB0 = mkdesc64(sb + 32768) + 2 * ks;
                            uint64_t dB1 = mkdesc64(sb + 49152) + 2 * ks;
                            uint32_t d   = tmem + 256 * h;
                            uint32_t en  = (c == 0 && ks == 0) ? 0u : 1u;
                            mma_f16_ss(d, dA0, dB0, IDESC, en);
                            mma_f16_ss(d, dA0, dB1, IDESC, 1u);
                            mma_f16_ss(d, dA1, dB0, IDESC, 1u);
                        }
                    }
                    mma_commit(mbar0 + 8 * (c % 3));
                }

                if (c >= 1) mbar_wait(mbar0 + 8 * ((c - 1) % 3), ((c - 1) / 3) & 1);

                if (c + 2 < NCHUNK) {
                    load_b(c + 2, (c + 2) % 3);
                    sts_a((c + 2) % 3, xr);
                }
            }
            mbar_wait(mbar0 + 8 * ((NCHUNK - 1) % 3), ((NCHUNK - 1) / 3) & 1);
            tcgen05_fence_after();

            {
                int h = wid >> 2, sub = wid & 3;
                size_t row = m0 + h * 128 + sub * 32 + lane;
                float* cp = g_pre + row * N_CAT + n0;
                const float sc = 1.0f / 1024.0f;
                #pragma unroll
                for (int cb = 0; cb < 8; cb += 2) {
                    uint32_t r0[32], r1[32];
                    LDTM_X32(r0, tmem + h * 256 + cb * 32);
                    LDTM_X32(r1, tmem + h * 256 + cb * 32 + 32);
                    tmem_wait_ld();
                    #pragma unroll
                    for (int j = 0; j < 32; j += 4) {
                        float4 v;
                        v.x = __uint_as_float(r0[j + 0]) * sc + g_bias[n0 + cb * 32 + j + 0];
                        v.y = __uint_as_float(r0[j + 1]) * sc + g_bias[n0 + cb * 32 + j + 1];
                        v.z = __uint_as_float(r0[j + 2]) * sc + g_bias[n0 + cb * 32 + j + 2];
                        v.w = __uint_as_float(r0[j + 3]) * sc + g_bias[n0 + cb * 32 + j + 3];
                        *(float4*)(cp + cb * 32 + j) = v;
                    }
                    #pragma unroll
                    for (int j = 0; j < 32; j += 4) {
                        float4 v;
                        v.x = __uint_as_float(r1[j + 0]) * sc + g_bias[n0 + (cb + 1) * 32 + j + 0];
                        v.y = __uint_as_float(r1[j + 1]) * sc + g_bias[n0 + (cb + 1) * 32 + j + 1];
                        v.z = __uint_as_float(r1[j + 2]) * sc + g_bias[n0 + (cb + 1) * 32 + j + 2];
                        v.w = __uint_as_float(r1[j + 3]) * sc + g_bias[n0 + (cb + 1) * 32 + j + 3];
                        *(float4*)(cp + (cb + 1) * 32 + j) = v;
                    }
                }
            }
            BAR_GEMM();                                  // all tile stores done
            if (tid == 0) {
                __threadfence();                         // release
                atomicAdd(&g_done[bb], 1u);
            }
            if (wid == 0) tmem_dealloc(tmem, 512);

#else
            // ========= HMMA fallback (compute_103): four 128x128 sub-tiles ===
            const uint32_t sb = smem_u32(smem);
            const int wm = (wid >> 2) * 64;
            const int wn = (wid & 3) * 32;
            #define ROWB 80
            #define SPL_BYTES (128 * ROWB)
            #define HSTAGE (4 * SPL_BYTES)
            #pragma unroll 1
            for (int mh = 0; mh < 2; mh++) {
                const size_t m0h = m0 + 128 * mh;
                #pragma unroll 1
                for (int nh = 0; nh < 2; nh++) {
                    const int n0h = n0 + 128 * nh;
                    float c[4][4][4];
                    #pragma unroll
                    for (int i = 0; i < 4; i++)
                        #pragma unroll
                        for (int j = 0; j < 4; j++)
                            #pragma unroll
                            for (int k = 0; k < 4; k++) c[i][j][k] = 0.f;
                    auto load_stage = [&](int cc, int st) {
                        char* basep = smem + st * HSTAGE;
                        uint32_t base = sb + st * HSTAGE;
                        #pragma unroll
                        for (int i = 0; i < 4; i++) {
                            int u = tid + 256 * i;
                            int r = u >> 3, jj = u & 7;
                            float4 xv = *(const float4*)(x + (m0h + r) * K_DIM + cc * 32 + 4 * jj);
                            uint2 hi, lo;
                            split4(xv, hi, lo);
                            *(uint2*)(basep + r * ROWB + jj * 8)             = hi;
                            *(uint2*)(basep + SPL_BYTES + r * ROWB + jj * 8) = lo;
                        }
                        #pragma unroll
                        for (int i = 0; i < 4; i++) {
                            int u = tid + 256 * i;
                            int p = u >> 9, r = (u >> 2) & 127, j = u & 3;
                            const __half* src = (p ? g_ws1 : g_ws0) + (size_t)(n0h + r) * K_DIM + cc * 32 + j * 8;
                            cp16(base + 2 * SPL_BYTES + p * SPL_BYTES + r * ROWB + j * 16, src);
                        }
                        cp_commit();
                    };
                    auto compute_stage = [&](int st) {
                        uint32_t Ab = sb + st * HSTAGE;
                        uint32_t Bb = Ab + 2 * SPL_BYTES;
                        #pragma unroll
                        for (int kk = 0; kk < 2; kk++) {
                            uint32_t a[2][4][4];
                            uint32_t b[2][4][2];
                            #pragma unroll
                            for (int p = 0; p < 2; p++)
                                #pragma unroll
                                for (int mi = 0; mi < 4; mi++) {
                                    uint32_t addr = Ab + p * SPL_BYTES
                                                  + (wm + 16 * mi + (lane & 15)) * ROWB
                                                  + kk * 32 + (lane >> 4) * 16;
                                    ldsm4(a[p][mi], addr);
                                }
                            #pragma unroll
                            for (int p = 0; p < 2; p++)
                                #pragma unroll
                                for (int jj = 0; jj < 2; jj++) {
                                    uint32_t nr = wn + 16 * jj + ((lane >> 4) & 1) * 8 + (lane & 7);
                                    uint32_t addr = Bb + p * SPL_BYTES + nr * ROWB
                                                  + kk * 32 + ((lane >> 3) & 1) * 16;
                                    uint32_t r4[4];
                                    ldsm4(r4, addr);
                                    b[p][2 * jj][0]     = r4[0]; b[p][2 * jj][1]     = r4[1];
                                    b[p][2 * jj + 1][0] = r4[2]; b[p][2 * jj + 1][1] = r4[3];
                                }
                            #pragma unroll
                            for (int mi = 0; mi < 4; mi++)
                                #pragma unroll
                                for (int nj = 0; nj < 4; nj++) {
                                    mma16816(c[mi][nj], a[0][mi], b[0][nj]);
                                    mma16816(c[mi][nj], a[0][mi], b[1][nj]);
                                    mma16816(c[mi][nj], a[1][mi], b[0][nj]);
                                }
                        }
                    };
                    load_stage(0, 0);
                    #pragma unroll 1
                    for (int cc = 0; cc < K_DIM / 32; cc++) {
                        cp_wait0();
                        BAR_GEMM();
                        if (cc + 1 < K_DIM / 32) load_stage(cc + 1, (cc + 1) & 1);
                        compute_stage(cc & 1);
                    }
                    BAR_GEMM();
                    const float sc = 1.0f / 1024.0f;
                    const int g = lane >> 2, t4 = lane & 3;
                    #pragma unroll
                    for (int mi = 0; mi < 4; mi++) {
                        #pragma unroll
                        for (int nj = 0; nj < 4; nj++) {
                            int col = n0h + wn + 8 * nj + t4 * 2;
                            float b0 = g_bias[col], b1 = g_bias[col + 1];
                            size_t row = m0h + wm + 16 * mi + g;
                            float2 v0 = {c[mi][nj][0] * sc + b0, c[mi][nj][1] * sc + b1};
                            *(float2*)(g_pre + row * N_CAT + col) = v0;
                            float2 v1 = {c[mi][nj][2] * sc + b0, c[mi][nj][3] * sc + b1};
                            *(float2*)(g_pre + (row + 8) * N_CAT + col) = v1;
                        }
                    }
                }
            }
            BAR_GEMM();
            if (tid == 0) {
                __threadfence();
                atomicAdd(&g_done[bb], 1u);
            }
            #undef ROWB
            #undef SPL_BYTES
            #undef HSTAGE
#endif
        }
        return;
    }

    // ================== Recur part (warps 8-11) ==================
    {
        const int rg = cid - 64 * LAG;               // rowgroup handled by this CTA
        if (rg < 0 || rg >= N_GCTA) return;
        const int rw = wid - 8;                      // 0..3
        const int l  = lane;
        const int r  = rg * 4 + rw;                  // batch row

        // wait for b-block rg>>6 fully materialized (64 gemm CTAs arrived)
        {
            const unsigned* flag = &g_done[rg >> 6];
            unsigned v = 0;
            do {
                if (l == 0) v = poll_acq(flag);
                v = __shfl_sync(0xffffffffu, v, 0);
                if (v >= 64u) break;
                npause();
            } while (true);
        }

        float m1[16], m2[16], m3[16];
        #pragma unroll
        for (int i = 0; i < 16; i++) { m1[i] = 0.f; m2[i] = 0.f; m3[i] = 0.f; }
        float oacc[OUT_N] = {0.f, 0.f, 0.f, 0.f, 0.f, 0.f, 0.f};

        for (int t = 0; t < T_STEPS; t++) {
            const float* pre = g_pre + ((size_t)t * B_ROWS + r) * N_CAT;
            unsigned bal[16];

            float4 pa[4], pb[4];
            #pragma unroll
            for (int m = 0; m < 4; m++) pa[m] = *(const float4*)(pre + 128 * m + 4 * l);
            #pragma unroll
            for (int m = 0; m < 4; m++) pb[m] = *(const float4*)(pre + HID + 128 * m + 4 * l);

            // ---- LIF1 ----
            #pragma unroll
            for (int m = 0; m < 4; m++) {
                float pv[4] = {pa[m].x, pa[m].y, pa[m].z, pa[m].w};
                #pragma unroll
                for (int q = 0; q < 4; q++) {
                    float v = 0.5f * (m1[4 * m + q] + pv[q]);
                    bool  s = v > 1.0f;
                    m1[4 * m + q] = s ? 0.f : v;
                    bal[4 * m + q] = __ballot_sync(0xffffffffu, s);
                }
            }

            // ---- pc_pre = gc @ W_pc + b_pc ----
            float a2[16];
            #pragma unroll
            for (int m = 0; m < 4; m++) {
                float4 bv = *(const float4*)(b_pc + 128 * m + 4 * l);
                a2[4 * m + 0] = bv.x; a2[4 * m + 1] = bv.y;
                a2[4 * m + 2] = bv.z; a2[4 * m + 3] = bv.w;
            }
            {
                unsigned any = 0;
                #pragma unroll
                for (int mw = 0; mw < 16; mw++) any |= bal[mw];
                if (any) {
                    #pragma unroll
                    for (int mw = 0; mw < 16; mw++) {
                        unsigned mm = bal[mw];
                        while (mm) {
                            int bit = __ffs(mm) - 1;
                            mm &= mm - 1;
                            int row2 = 128 * (mw >> 2) + 4 * bit + (mw & 3);
                            const float* wr = W_pc + (size_t)row2 * HID;
                            #pragma unroll
                            for (int m = 0; m < 4; m++) {
                                float4 wv = *(const float4*)(wr + 128 * m + 4 * l);
                                a2[4 * m + 0] += wv.x; a2[4 * m + 1] += wv.y;
                                a2[4 * m + 2] += wv.z; a2[4 * m + 3] += wv.w;
                            }
                        }
                    }
                }
            }

            // ---- LIF2 ----
            #pragma unroll
            for (int i = 0; i < 16; i++) {
                float v = 0.5f * (m2[i] + a2[i]);
                bool  s = v > 1.0f;
                m2[i] = s ? 0.f : v;
                bal[i] = __ballot_sync(0xffffffffu, s);
            }

            // ---- d1_pre = x-part + pc @ W_d1_bottom ----
            float a3[16];
            #pragma unroll
            for (int m = 0; m < 4; m++) {
                a3[4 * m + 0] = pb[m].x; a3[4 * m + 1] = pb[m].y;
                a3[4 * m + 2] = pb[m].z; a3[4 * m + 3] = pb[m].w;
            }
            {
                unsigned any = 0;
                #pragma unroll
                for (int mw = 0; mw < 16; mw++) any |= bal[mw];
                if (any) {
                    #pragma unroll
                    for (int mw = 0; mw < 16; mw++) {
                        unsigned mm = bal[mw];
                        while (mm) {
                            int bit = __ffs(mm) - 1;
                            mm &= mm - 1;
                            int row2 = HID + 128 * (mw >> 2) + 4 * bit + (mw & 3);
                            const float* wr = W_d1 + (size_t)row2 * HID;
                            #pragma unroll
                            for (int m = 0; m < 4; m++) {
                                float4 wv = *(const float4*)(wr + 128 * m + 4 * l);
                                a3[4 * m + 0] += wv.x; a3[4 * m + 1] += wv.y;
                                a3[4 * m + 2] += wv.z; a3[4 * m + 3] += wv.w;
                            }
                        }
                    }
                }
            }

            // ---- LIF3 -> readout ----
            #pragma unroll
            for (int i = 0; i < 16; i++) {
                float v = 0.5f * (m3[i] + a3[i]);
                bool  s = v > 1.0f;
                m3[i] = s ? 0.f : v;
                if (s) {
                    int j = 128 * (i >> 2) + 4 * l + (i & 3);
                    const float* wr = W_d2 + (size_t)j * OUT_N;
                    #pragma unroll
                    for (int o = 0; o < OUT_N; o++) oacc[o] += wr[o];
                }
            }
        }

        #pragma unroll
        for (int o = 0; o < OUT_N; o++) {
            float v = oacc[o];
            #pragma unroll
            for (int off = 16; off; off >>= 1) v += __shfl_down_sync(0xffffffffu, v, off);
            if (l == 0) out[(size_t)r * OUT_N + o] = v * (1.0f / (float)T_STEPS) + b_d2[o];
        }
    }
}

// ---------------------------------------------------------------------------
extern "C" void kernel_launch(void* const* d_in, const int* in_sizes, int n_in,
                              void* d_out, int out_size)
{
    const float* x    = (const float*)d_in[0];
    const float* W_gc = (const float*)d_in[1];
    const float* b_gc = (const float*)d_in[2];
    const float* W_pc = (const float*)d_in[3];
    const float* b_pc = (const float*)d_in[4];
    const float* W_d1 = (const float*)d_in[5];
    const float* b_d1 = (const float*)d_in[6];
    const float* W_d2 = (const float*)d_in[7];
    const float* b_d2 = (const float*)d_in[8];
    float* out = (float*)d_out;
    (void)in_sizes; (void)n_in; (void)out_size;

    cudaFuncSetAttribute(fused_kernel, cudaFuncAttributeMaxDynamicSharedMemorySize, GEMM_SMEM);

    convert_w_kernel<<<(N_CAT * K_DIM) / 256, 256>>>(W_gc, W_d1, b_gc, b_d1);

    fused_kernel<<<N_CTA, 384, GEMM_SMEM>>>(x, W_pc, b_pc, W_d1, W_d2, b_d2, out);
}